// round 1
// baseline (speedup 1.0000x reference)
#include <cuda_runtime.h>
#include <math.h>

#define B_   2
#define S_   2048
#define HID_ 2048
#define H_   16
#define KV_  8
#define D_   128
#define MROWS (B_ * S_)   // 4096

// Scratch (allocation-free rule: __device__ globals)
__device__ float g_q[(size_t)MROWS * H_ * D_];    // 33.5 MB
__device__ float g_k[(size_t)MROWS * KV_ * D_];   // 16.8 MB
__device__ float g_v[(size_t)MROWS * KV_ * D_];   // 16.8 MB
__device__ float g_att[(size_t)MROWS * H_ * D_];  // 33.5 MB

// ---------------------------------------------------------------------------
// NT SGEMM: C[m,n] = sum_k A[m*K+k] * W[n*K+k]
// BM=BN=128, BK=8, 256 threads, 8x8 microtile per thread.
// Requires M%128==0, N%128==0, K%8==0 (true for all our shapes).
// ---------------------------------------------------------------------------
__global__ __launch_bounds__(256) void sgemm_nt(
    const float* __restrict__ A, const float* __restrict__ W,
    float* __restrict__ C, int M, int N, int K)
{
    __shared__ float As[8][128];
    __shared__ float Bs[8][128];
    const int tid = threadIdx.x;
    const int tx  = tid & 15;       // 0..15, cols tx*8..tx*8+7
    const int ty  = tid >> 4;       // 0..15, rows ty*8..ty*8+7
    const int m0  = blockIdx.y << 7;
    const int n0  = blockIdx.x << 7;
    const int lrow = tid >> 1;      // 0..127
    const int lk   = (tid & 1) << 2; // 0 or 4

    const float* Ap = A + (size_t)(m0 + lrow) * K + lk;
    const float* Wp = W + (size_t)(n0 + lrow) * K + lk;

    float acc[8][8];
#pragma unroll
    for (int i = 0; i < 8; i++)
#pragma unroll
        for (int j = 0; j < 8; j++) acc[i][j] = 0.f;

    for (int k0 = 0; k0 < K; k0 += 8) {
        float4 av = *(const float4*)(Ap + k0);
        float4 wv = *(const float4*)(Wp + k0);
        As[lk + 0][lrow] = av.x; As[lk + 1][lrow] = av.y;
        As[lk + 2][lrow] = av.z; As[lk + 3][lrow] = av.w;
        Bs[lk + 0][lrow] = wv.x; Bs[lk + 1][lrow] = wv.y;
        Bs[lk + 2][lrow] = wv.z; Bs[lk + 3][lrow] = wv.w;
        __syncthreads();
#pragma unroll
        for (int kk = 0; kk < 8; kk++) {
            float4 a0 = *(const float4*)&As[kk][ty * 8];
            float4 a1 = *(const float4*)&As[kk][ty * 8 + 4];
            float4 b0 = *(const float4*)&Bs[kk][tx * 8];
            float4 b1 = *(const float4*)&Bs[kk][tx * 8 + 4];
            float a[8] = {a0.x, a0.y, a0.z, a0.w, a1.x, a1.y, a1.z, a1.w};
            float b[8] = {b0.x, b0.y, b0.z, b0.w, b1.x, b1.y, b1.z, b1.w};
#pragma unroll
            for (int i = 0; i < 8; i++)
#pragma unroll
                for (int j = 0; j < 8; j++) acc[i][j] += a[i] * b[j];
        }
        __syncthreads();
    }
#pragma unroll
    for (int i = 0; i < 8; i++) {
        float* Cp = C + (size_t)(m0 + ty * 8 + i) * N + n0 + tx * 8;
        *(float4*)Cp       = make_float4(acc[i][0], acc[i][1], acc[i][2], acc[i][3]);
        *(float4*)(Cp + 4) = make_float4(acc[i][4], acc[i][5], acc[i][6], acc[i][7]);
    }
}

// ---------------------------------------------------------------------------
// Per-head RMSNorm (over D=128) + RoPE, in place.
// X: [rows, 128] where row = (b*S + s)*nheads + h. pe: [B,S,128]=cat(cos,sin).
// One block (128 threads) per row.
// ---------------------------------------------------------------------------
__global__ __launch_bounds__(128) void rmsnorm_rope(
    float* __restrict__ X, const float* __restrict__ pe,
    const float* __restrict__ w, int nheads)
{
    __shared__ float sv[128];
    __shared__ float wsum[4];
    const int row = blockIdx.x;
    const int t   = threadIdx.x;
    const int bs  = row / nheads;   // = b*S + s

    float v  = X[(size_t)row * 128 + t];
    float ss = v * v;
#pragma unroll
    for (int o = 16; o > 0; o >>= 1) ss += __shfl_xor_sync(0xffffffffu, ss, o);
    if ((t & 31) == 0) wsum[t >> 5] = ss;
    __syncthreads();
    float tot = wsum[0] + wsum[1] + wsum[2] + wsum[3];
    float r   = rsqrtf(tot * (1.f / 128.f) + 1e-6f);
    float xn  = v * r * w[t];
    sv[t] = xn;
    __syncthreads();

    int   d = (t < 64) ? t : (t - 64);
    float c = pe[(size_t)bs * 128 + d];
    float s = pe[(size_t)bs * 128 + 64 + d];
    float other = (t < 64) ? sv[t + 64] : sv[t - 64];
    float out   = (t < 64) ? (xn * c - other * s) : (other * s + xn * c);
    X[(size_t)row * 128 + t] = out;
}

// ---------------------------------------------------------------------------
// Causal flash attention, GQA (kv head = h/2).
// Q,O: [B,S,H,D]; K,V: [B,S,KV,D]. BR=BC=64, 256 threads.
// S-tile: 16x16 threads, 4x4 each. PV: rows ty*4 (consistent), cols tx*8.
// ---------------------------------------------------------------------------
#define QSTR 129
#define KSTR 129
#define VSTR 132
#define PSTR 68
#define FLASH_SMEM ((64 * QSTR + 64 * KSTR + 64 * VSTR + 64 * PSTR) * 4)

__global__ __launch_bounds__(256) void flash_attn(
    const float* __restrict__ Q, const float* __restrict__ Kg,
    const float* __restrict__ Vg, float* __restrict__ O)
{
    extern __shared__ float smf[];
    float* s_q = smf;
    float* s_k = s_q + 64 * QSTR;
    float* s_v = s_k + 64 * KSTR;   // byte offset 66048, 16B aligned
    float* s_p = s_v + 64 * VSTR;

    const int tid = threadIdx.x;
    const int tx  = tid & 15, ty = tid >> 4;
    const int q0  = blockIdx.x << 6;
    const int h   = blockIdx.y, b = blockIdx.z;
    const int kvh = h >> 1;

    // Load Q tile [64][128]
#pragma unroll
    for (int j = 0; j < 8; j++) {
        int idx = tid + j * 256;
        int r = idx >> 5, c4 = (idx & 31) << 2;
        float4 qv = *(const float4*)(Q + (((size_t)b * S_ + q0 + r) * H_ + h) * D_ + c4);
        s_q[r * QSTR + c4 + 0] = qv.x;
        s_q[r * QSTR + c4 + 1] = qv.y;
        s_q[r * QSTR + c4 + 2] = qv.z;
        s_q[r * QSTR + c4 + 3] = qv.w;
    }

    float m_i[4], l_i[4], acc[4][8];
#pragma unroll
    for (int i = 0; i < 4; i++) {
        m_i[i] = -1e30f; l_i[i] = 0.f;
#pragma unroll
        for (int j = 0; j < 8; j++) acc[i][j] = 0.f;
    }

    const float scale = 0.08838834764831845f;  // 1/sqrt(128)
    const int ntiles = blockIdx.x + 1;

    for (int kt = 0; kt < ntiles; kt++) {
        const int k0 = kt << 6;
        __syncthreads();  // prior PV reads of s_k/s_v done
        // Load K/V tiles [64][128]
#pragma unroll
        for (int j = 0; j < 8; j++) {
            int idx = tid + j * 256;
            int r = idx >> 5, c4 = (idx & 31) << 2;
            size_t base = (((size_t)b * S_ + k0 + r) * KV_ + kvh) * D_ + c4;
            float4 kv = *(const float4*)(Kg + base);
            s_k[r * KSTR + c4 + 0] = kv.x;
            s_k[r * KSTR + c4 + 1] = kv.y;
            s_k[r * KSTR + c4 + 2] = kv.z;
            s_k[r * KSTR + c4 + 3] = kv.w;
            float4 vv = *(const float4*)(Vg + base);
            *(float4*)&s_v[r * VSTR + c4] = vv;
        }
        __syncthreads();

        // S = scale * Q K^T  (4x4 per thread)
        float s[4][4];
#pragma unroll
        for (int i = 0; i < 4; i++)
#pragma unroll
            for (int j = 0; j < 4; j++) s[i][j] = 0.f;
#pragma unroll 4
        for (int k = 0; k < 128; k++) {
            float a[4], bb[4];
#pragma unroll
            for (int i = 0; i < 4; i++) a[i]  = s_q[(ty * 4 + i) * QSTR + k];
#pragma unroll
            for (int j = 0; j < 4; j++) bb[j] = s_k[(tx * 4 + j) * KSTR + k];
#pragma unroll
            for (int i = 0; i < 4; i++)
#pragma unroll
                for (int j = 0; j < 4; j++) s[i][j] += a[i] * bb[j];
        }

        // Online softmax per row (reduce across 16 lanes)
        const bool diag = (kt == blockIdx.x);
#pragma unroll
        for (int i = 0; i < 4; i++) {
            const int rr = ty * 4 + i;
#pragma unroll
            for (int j = 0; j < 4; j++) {
                float val = s[i][j] * scale;
                if (diag && (tx * 4 + j) > rr) val = -1e30f;
                s[i][j] = val;
            }
            float mx = fmaxf(fmaxf(s[i][0], s[i][1]), fmaxf(s[i][2], s[i][3]));
#pragma unroll
            for (int o = 8; o > 0; o >>= 1) mx = fmaxf(mx, __shfl_xor_sync(0xffffffffu, mx, o));
            float mnew = fmaxf(m_i[i], mx);
            float sum = 0.f;
#pragma unroll
            for (int j = 0; j < 4; j++) {
                float p = __expf(s[i][j] - mnew);
                s[i][j] = p;
                sum += p;
            }
#pragma unroll
            for (int o = 8; o > 0; o >>= 1) sum += __shfl_xor_sync(0xffffffffu, sum, o);
            float alpha = __expf(m_i[i] - mnew);
            l_i[i] = l_i[i] * alpha + sum;
            m_i[i] = mnew;
#pragma unroll
            for (int j = 0; j < 8; j++) acc[i][j] *= alpha;
#pragma unroll
            for (int j = 0; j < 4; j++) s_p[(ty * 4 + i) * PSTR + tx * 4 + j] = s[i][j];
        }
        __syncthreads();

        // O += P @ V  (rows ty*4, cols tx*8)
#pragma unroll 2
        for (int c = 0; c < 64; c++) {
            float a[4];
#pragma unroll
            for (int i = 0; i < 4; i++) a[i] = s_p[(ty * 4 + i) * PSTR + c];
            float4 b0 = *(const float4*)&s_v[c * VSTR + tx * 8];
            float4 b1 = *(const float4*)&s_v[c * VSTR + tx * 8 + 4];
            float bv[8] = {b0.x, b0.y, b0.z, b0.w, b1.x, b1.y, b1.z, b1.w};
#pragma unroll
            for (int i = 0; i < 4; i++)
#pragma unroll
                for (int j = 0; j < 8; j++) acc[i][j] += a[i] * bv[j];
        }
    }

    // Epilogue
#pragma unroll
    for (int i = 0; i < 4; i++) {
        float inv = 1.f / l_i[i];
        float* Op = O + (((size_t)b * S_ + q0 + ty * 4 + i) * H_ + h) * D_ + tx * 8;
        *(float4*)Op       = make_float4(acc[i][0] * inv, acc[i][1] * inv,
                                         acc[i][2] * inv, acc[i][3] * inv);
        *(float4*)(Op + 4) = make_float4(acc[i][4] * inv, acc[i][5] * inv,
                                         acc[i][6] * inv, acc[i][7] * inv);
    }
}

// ---------------------------------------------------------------------------
extern "C" void kernel_launch(void* const* d_in, const int* in_sizes, int n_in,
                              void* d_out, int out_size)
{
    const float* x   = (const float*)d_in[0];
    const float* pe  = (const float*)d_in[1];
    const float* q_w = (const float*)d_in[2];
    const float* k_w = (const float*)d_in[3];
    const float* v_w = (const float*)d_in[4];
    const float* o_w = (const float*)d_in[5];
    const float* qnw = (const float*)d_in[6];
    const float* knw = (const float*)d_in[7];
    float* out = (float*)d_out;

    float *q, *k, *v, *att;
    cudaGetSymbolAddress((void**)&q,   g_q);
    cudaGetSymbolAddress((void**)&k,   g_k);
    cudaGetSymbolAddress((void**)&v,   g_v);
    cudaGetSymbolAddress((void**)&att, g_att);

    cudaFuncSetAttribute(flash_attn, cudaFuncAttributeMaxDynamicSharedMemorySize,
                         FLASH_SMEM);

    // Projections
    sgemm_nt<<<dim3(16, 32), 256>>>(x, q_w, q, MROWS, H_ * D_, HID_);
    sgemm_nt<<<dim3(8, 32),  256>>>(x, k_w, k, MROWS, KV_ * D_, HID_);
    sgemm_nt<<<dim3(8, 32),  256>>>(x, v_w, v, MROWS, KV_ * D_, HID_);

    // Per-head RMSNorm + RoPE (in place)
    rmsnorm_rope<<<MROWS * H_,  128>>>(q, pe, qnw, H_);
    rmsnorm_rope<<<MROWS * KV_, 128>>>(k, pe, knw, KV_);

    // Causal GQA flash attention
    flash_attn<<<dim3(S_ / 64, H_, B_), 256, FLASH_SMEM>>>(q, k, v, att);

    // Output projection
    sgemm_nt<<<dim3(16, 32), 256>>>(att, o_w, out, MROWS, HID_, HID_);
}

// round 5
// speedup vs baseline: 1.6662x; 1.6662x over previous
#include <cuda_runtime.h>
#include <cuda_bf16.h>
#include <math.h>
#include <stdint.h>

#define B_   2
#define S_   2048
#define HID_ 2048
#define H_   16
#define KV_  8
#define D_   128
#define MROWS (B_ * S_)   // 4096

// ---------------------------------------------------------------------------
// Scratch (__device__ globals; allocation-free rule)
// ---------------------------------------------------------------------------
__device__ float g_q[(size_t)MROWS * H_ * D_];
__device__ float g_k[(size_t)MROWS * KV_ * D_];
__device__ float g_v[(size_t)MROWS * KV_ * D_];
__device__ __nv_bfloat16 g_xh[(size_t)MROWS * HID_];
__device__ __nv_bfloat16 g_xl[(size_t)MROWS * HID_];
__device__ __nv_bfloat16 g_qwh[(size_t)H_ * D_ * HID_];
__device__ __nv_bfloat16 g_qwl[(size_t)H_ * D_ * HID_];
__device__ __nv_bfloat16 g_kwh[(size_t)KV_ * D_ * HID_];
__device__ __nv_bfloat16 g_kwl[(size_t)KV_ * D_ * HID_];
__device__ __nv_bfloat16 g_vwh[(size_t)KV_ * D_ * HID_];
__device__ __nv_bfloat16 g_vwl[(size_t)KV_ * D_ * HID_];
__device__ __nv_bfloat16 g_owh[(size_t)HID_ * H_ * D_];
__device__ __nv_bfloat16 g_owl[(size_t)HID_ * H_ * D_];
__device__ __nv_bfloat16 g_ath[(size_t)MROWS * H_ * D_];
__device__ __nv_bfloat16 g_atl[(size_t)MROWS * H_ * D_];

// ---------------------------------------------------------------------------
// Helpers
// ---------------------------------------------------------------------------
__device__ __forceinline__ uint32_t smem_u32(const void* p) {
    uint32_t a;
    asm("{ .reg .u64 t; cvta.to.shared.u64 t, %1; cvt.u32.u64 %0, t; }"
        : "=r"(a) : "l"(p));
    return a;
}

__device__ __forceinline__ void ldsm_x4(uint32_t& r0, uint32_t& r1,
                                        uint32_t& r2, uint32_t& r3, uint32_t addr) {
    asm volatile("ldmatrix.sync.aligned.m8n8.x4.shared.b16 {%0,%1,%2,%3}, [%4];"
                 : "=r"(r0), "=r"(r1), "=r"(r2), "=r"(r3) : "r"(addr));
}

__device__ __forceinline__ void mma_bf16(float* c, const uint32_t* a, const uint32_t* b) {
    asm volatile("mma.sync.aligned.m16n8k16.row.col.f32.bf16.bf16.f32 "
                 "{%0,%1,%2,%3}, {%4,%5,%6,%7}, {%8,%9}, {%0,%1,%2,%3};"
                 : "+f"(c[0]), "+f"(c[1]), "+f"(c[2]), "+f"(c[3])
                 : "r"(a[0]), "r"(a[1]), "r"(a[2]), "r"(a[3]),
                   "r"(b[0]), "r"(b[1]));
}

// ---------------------------------------------------------------------------
// split fp32 -> (bf16 hi, bf16 lo)
// ---------------------------------------------------------------------------
__global__ __launch_bounds__(256) void split_bf16(
    const float4* __restrict__ s, __nv_bfloat162* __restrict__ h,
    __nv_bfloat162* __restrict__ l, int n4)
{
    int i = blockIdx.x * 256 + threadIdx.x;
    if (i >= n4) return;
    float4 v = s[i];
    __nv_bfloat16 hx = __float2bfloat16(v.x);
    __nv_bfloat16 hy = __float2bfloat16(v.y);
    __nv_bfloat16 hz = __float2bfloat16(v.z);
    __nv_bfloat16 hw = __float2bfloat16(v.w);
    __nv_bfloat16 lx = __float2bfloat16(v.x - __bfloat162float(hx));
    __nv_bfloat16 ly = __float2bfloat16(v.y - __bfloat162float(hy));
    __nv_bfloat16 lz = __float2bfloat16(v.z - __bfloat162float(hz));
    __nv_bfloat16 lw = __float2bfloat16(v.w - __bfloat162float(hw));
    h[2 * i]     = __nv_bfloat162(hx, hy);
    h[2 * i + 1] = __nv_bfloat162(hz, hw);
    l[2 * i]     = __nv_bfloat162(lx, ly);
    l[2 * i + 1] = __nv_bfloat162(lz, lw);
}

// ---------------------------------------------------------------------------
// bf16x3 mma.sync GEMM: C[m,n] = sum_k A[m,k]*B[n,k]  (both K-major)
// C = Ah*Bh + Ah*Bl + Al*Bh
// BM=BN=128, BK=32, 256 threads (8 warps as 2x4, each 64x32).
// smem per stage: Ah, Al, Bh, Bl tiles, each 128 rows x 32 bf16, row stride
// 40 bf16 (80 B) -> conflict-free ldmatrix (16B-unit stride 5).
// ---------------------------------------------------------------------------
#define GK_      32
#define RSTR_B   80u                 // bytes per smem row
#define TILE_B   (128u * RSTR_B)     // 10240
#define STAGE_B  (4u * TILE_B)       // 40960
#define GEMM_SMEM (2 * 40960)

__device__ __forceinline__ void g_fill(
    uint32_t dst, const __nv_bfloat16* Ah, const __nv_bfloat16* Al,
    const __nv_bfloat16* Bh, const __nv_bfloat16* Bl,
    int m0, int n0, int K, int k0, int tid)
{
#pragma unroll
    for (int i = 0; i < 8; i++) {
        int idx = tid + i * 256;
        int t   = idx >> 9;          // tile 0..3
        int rem = idx & 511;
        int r   = rem >> 2;
        int seg = rem & 3;
        const __nv_bfloat16* src;
        if      (t == 0) src = Ah + (size_t)(m0 + r) * K + k0 + seg * 8;
        else if (t == 1) src = Al + (size_t)(m0 + r) * K + k0 + seg * 8;
        else if (t == 2) src = Bh + (size_t)(n0 + r) * K + k0 + seg * 8;
        else             src = Bl + (size_t)(n0 + r) * K + k0 + seg * 8;
        uint32_t d = dst + (uint32_t)t * TILE_B + (uint32_t)r * RSTR_B + (uint32_t)seg * 16u;
        asm volatile("cp.async.cg.shared.global [%0], [%1], 16;"
                     :: "r"(d), "l"(src));
    }
}

__global__ __launch_bounds__(256, 1) void gemm_bf16x3(
    const __nv_bfloat16* __restrict__ Ah, const __nv_bfloat16* __restrict__ Al,
    const __nv_bfloat16* __restrict__ Bh, const __nv_bfloat16* __restrict__ Bl,
    float* __restrict__ C, int N, int K)
{
    extern __shared__ __align__(128) char smem[];
    const uint32_t sb  = smem_u32(smem);
    const int tid  = threadIdx.x;
    const int wid  = tid >> 5, lane = tid & 31;
    const int m0   = blockIdx.y << 7, n0 = blockIdx.x << 7;
    const int wm   = (wid >> 2) << 6;   // 0 or 64
    const int wn   = (wid & 3)  << 5;   // 0,32,64,96

    // per-lane ldmatrix offsets (within a stage)
    // A tiles: lanes 0-15 -> rows (lane&15), lanes>>4 -> +16B (k cols 8-15)
    const uint32_t aoff = (uint32_t)(wm + (lane & 15)) * RSTR_B + (uint32_t)((lane >> 4) * 16);
    // B tiles (x4 covers n16 x k16)
    const uint32_t boff = (uint32_t)(wn + ((lane >> 4) << 3) + (lane & 7)) * RSTR_B
                        + (uint32_t)(((lane >> 3) & 1) * 16);

    float acc[4][4][4];
#pragma unroll
    for (int mi = 0; mi < 4; mi++)
#pragma unroll
        for (int ni = 0; ni < 4; ni++)
#pragma unroll
            for (int r = 0; r < 4; r++) acc[mi][ni][r] = 0.f;

    g_fill(sb, Ah, Al, Bh, Bl, m0, n0, K, 0, tid);
    asm volatile("cp.async.commit_group;");

    const int nit = K / GK_;
    for (int it = 0; it < nit; ++it) {
        const int cur = it & 1;
        if (it + 1 < nit) {
            g_fill(sb + (uint32_t)(cur ^ 1) * STAGE_B, Ah, Al, Bh, Bl,
                   m0, n0, K, (it + 1) * GK_, tid);
            asm volatile("cp.async.commit_group;");
            asm volatile("cp.async.wait_group 1;");
        } else {
            asm volatile("cp.async.wait_group 0;");
        }
        __syncthreads();

        const uint32_t stg = sb + (uint32_t)cur * STAGE_B;
        const uint32_t sAh = stg;
        const uint32_t sAl = stg + TILE_B;
        const uint32_t sBh = stg + 2u * TILE_B;
        const uint32_t sBl = stg + 3u * TILE_B;

#pragma unroll
        for (int kh = 0; kh < 2; kh++) {            // k16 halves of BK=32
            const uint32_t kb = (uint32_t)kh * 32u; // byte offset (16 bf16)
            uint32_t ah[4][4], al[4][4], bh[4][2], bl[4][2];
#pragma unroll
            for (int mi = 0; mi < 4; mi++) {
                ldsm_x4(ah[mi][0], ah[mi][1], ah[mi][2], ah[mi][3],
                        sAh + aoff + (uint32_t)(mi * 16) * RSTR_B + kb);
                ldsm_x4(al[mi][0], al[mi][1], al[mi][2], al[mi][3],
                        sAl + aoff + (uint32_t)(mi * 16) * RSTR_B + kb);
            }
#pragma unroll
            for (int nt = 0; nt < 2; nt++) {        // two n16 groups
                uint32_t r0, r1, r2, r3;
                ldsm_x4(r0, r1, r2, r3, sBh + boff + (uint32_t)(nt * 16) * RSTR_B + kb);
                bh[nt * 2 + 0][0] = r0; bh[nt * 2 + 0][1] = r1;
                bh[nt * 2 + 1][0] = r2; bh[nt * 2 + 1][1] = r3;
                ldsm_x4(r0, r1, r2, r3, sBl + boff + (uint32_t)(nt * 16) * RSTR_B + kb);
                bl[nt * 2 + 0][0] = r0; bl[nt * 2 + 0][1] = r1;
                bl[nt * 2 + 1][0] = r2; bl[nt * 2 + 1][1] = r3;
            }
#pragma unroll
            for (int mi = 0; mi < 4; mi++)
#pragma unroll
                for (int ni = 0; ni < 4; ni++) {
                    mma_bf16(acc[mi][ni], ah[mi], bh[ni]);
                    mma_bf16(acc[mi][ni], ah[mi], bl[ni]);
                    mma_bf16(acc[mi][ni], al[mi], bh[ni]);
                }
        }
        __syncthreads();
    }

    // epilogue: c0,c1 -> (row, col..col+1); c2,c3 -> (row+8, ...)
#pragma unroll
    for (int mi = 0; mi < 4; mi++) {
        const int row = m0 + wm + mi * 16 + (lane >> 2);
#pragma unroll
        for (int ni = 0; ni < 4; ni++) {
            const int col = n0 + wn + ni * 8 + (lane & 3) * 2;
            *(float2*)&C[(size_t)row * N + col] =
                make_float2(acc[mi][ni][0], acc[mi][ni][1]);
            *(float2*)&C[(size_t)(row + 8) * N + col] =
                make_float2(acc[mi][ni][2], acc[mi][ni][3]);
        }
    }
}

// ---------------------------------------------------------------------------
// Per-head RMSNorm (over D=128) + RoPE, in place. (unchanged from R1)
// ---------------------------------------------------------------------------
__global__ __launch_bounds__(128) void rmsnorm_rope(
    float* __restrict__ X, const float* __restrict__ pe,
    const float* __restrict__ w, int nheads)
{
    __shared__ float sv[128];
    __shared__ float wsum[4];
    const int row = blockIdx.x;
    const int t   = threadIdx.x;
    const int bs  = row / nheads;

    float v  = X[(size_t)row * 128 + t];
    float ss = v * v;
#pragma unroll
    for (int o = 16; o > 0; o >>= 1) ss += __shfl_xor_sync(0xffffffffu, ss, o);
    if ((t & 31) == 0) wsum[t >> 5] = ss;
    __syncthreads();
    float tot = wsum[0] + wsum[1] + wsum[2] + wsum[3];
    float r   = rsqrtf(tot * (1.f / 128.f) + 1e-6f);
    float xn  = v * r * w[t];
    sv[t] = xn;
    __syncthreads();

    int   d = (t < 64) ? t : (t - 64);
    float c = pe[(size_t)bs * 128 + d];
    float s = pe[(size_t)bs * 128 + 64 + d];
    float other = (t < 64) ? sv[t + 64] : sv[t - 64];
    float out   = (t < 64) ? (xn * c - other * s) : (other * s + xn * c);
    X[(size_t)row * 128 + t] = out;
}

// ---------------------------------------------------------------------------
// Causal flash attention, GQA (fp32, R1-passing core).
// Epilogue emits bf16 hi/lo split of att for the O projection.
// ---------------------------------------------------------------------------
#define QSTR 129
#define KSTR 129
#define VSTR 132
#define PSTR 68
#define FLASH_SMEM ((64 * QSTR + 64 * KSTR + 64 * VSTR + 64 * PSTR) * 4)

__global__ __launch_bounds__(256) void flash_attn(
    const float* __restrict__ Q, const float* __restrict__ Kg,
    const float* __restrict__ Vg,
    __nv_bfloat16* __restrict__ Oh, __nv_bfloat16* __restrict__ Ol)
{
    extern __shared__ float smf[];
    float* s_q = smf;
    float* s_k = s_q + 64 * QSTR;
    float* s_v = s_k + 64 * KSTR;
    float* s_p = s_v + 64 * VSTR;

    const int tid = threadIdx.x;
    const int tx  = tid & 15, ty = tid >> 4;
    const int q0  = blockIdx.x << 6;
    const int h   = blockIdx.y, b = blockIdx.z;
    const int kvh = h >> 1;

#pragma unroll
    for (int j = 0; j < 8; j++) {
        int idx = tid + j * 256;
        int r = idx >> 5, c4 = (idx & 31) << 2;
        float4 qv = *(const float4*)(Q + (((size_t)b * S_ + q0 + r) * H_ + h) * D_ + c4);
        s_q[r * QSTR + c4 + 0] = qv.x;
        s_q[r * QSTR + c4 + 1] = qv.y;
        s_q[r * QSTR + c4 + 2] = qv.z;
        s_q[r * QSTR + c4 + 3] = qv.w;
    }

    float m_i[4], l_i[4], acc[4][8];
#pragma unroll
    for (int i = 0; i < 4; i++) {
        m_i[i] = -1e30f; l_i[i] = 0.f;
#pragma unroll
        for (int j = 0; j < 8; j++) acc[i][j] = 0.f;
    }

    const float scale = 0.08838834764831845f;
    const int ntiles = blockIdx.x + 1;

    for (int kt = 0; kt < ntiles; kt++) {
        const int k0 = kt << 6;
        __syncthreads();
#pragma unroll
        for (int j = 0; j < 8; j++) {
            int idx = tid + j * 256;
            int r = idx >> 5, c4 = (idx & 31) << 2;
            size_t base = (((size_t)b * S_ + k0 + r) * KV_ + kvh) * D_ + c4;
            float4 kv = *(const float4*)(Kg + base);
            s_k[r * KSTR + c4 + 0] = kv.x;
            s_k[r * KSTR + c4 + 1] = kv.y;
            s_k[r * KSTR + c4 + 2] = kv.z;
            s_k[r * KSTR + c4 + 3] = kv.w;
            float4 vv = *(const float4*)(Vg + base);
            *(float4*)&s_v[r * VSTR + c4] = vv;
        }
        __syncthreads();

        float s[4][4];
#pragma unroll
        for (int i = 0; i < 4; i++)
#pragma unroll
            for (int j = 0; j < 4; j++) s[i][j] = 0.f;
#pragma unroll 4
        for (int k = 0; k < 128; k++) {
            float a[4], bb[4];
#pragma unroll
            for (int i = 0; i < 4; i++) a[i]  = s_q[(ty * 4 + i) * QSTR + k];
#pragma unroll
            for (int j = 0; j < 4; j++) bb[j] = s_k[(tx * 4 + j) * KSTR + k];
#pragma unroll
            for (int i = 0; i < 4; i++)
#pragma unroll
                for (int j = 0; j < 4; j++) s[i][j] += a[i] * bb[j];
        }

        const bool diag = (kt == blockIdx.x);
#pragma unroll
        for (int i = 0; i < 4; i++) {
            const int rr = ty * 4 + i;
#pragma unroll
            for (int j = 0; j < 4; j++) {
                float val = s[i][j] * scale;
                if (diag && (tx * 4 + j) > rr) val = -1e30f;
                s[i][j] = val;
            }
            float mx = fmaxf(fmaxf(s[i][0], s[i][1]), fmaxf(s[i][2], s[i][3]));
#pragma unroll
            for (int o = 8; o > 0; o >>= 1) mx = fmaxf(mx, __shfl_xor_sync(0xffffffffu, mx, o));
            float mnew = fmaxf(m_i[i], mx);
            float sum = 0.f;
#pragma unroll
            for (int j = 0; j < 4; j++) {
                float p = __expf(s[i][j] - mnew);
                s[i][j] = p;
                sum += p;
            }
#pragma unroll
            for (int o = 8; o > 0; o >>= 1) sum += __shfl_xor_sync(0xffffffffu, sum, o);
            float alpha = __expf(m_i[i] - mnew);
            l_i[i] = l_i[i] * alpha + sum;
            m_i[i] = mnew;
#pragma unroll
            for (int j = 0; j < 8; j++) acc[i][j] *= alpha;
#pragma unroll
            for (int j = 0; j < 4; j++) s_p[(ty * 4 + i) * PSTR + tx * 4 + j] = s[i][j];
        }
        __syncthreads();

#pragma unroll 2
        for (int c = 0; c < 64; c++) {
            float a[4];
#pragma unroll
            for (int i = 0; i < 4; i++) a[i] = s_p[(ty * 4 + i) * PSTR + c];
            float4 b0 = *(const float4*)&s_v[c * VSTR + tx * 8];
            float4 b1 = *(const float4*)&s_v[c * VSTR + tx * 8 + 4];
            float bv[8] = {b0.x, b0.y, b0.z, b0.w, b1.x, b1.y, b1.z, b1.w};
#pragma unroll
            for (int i = 0; i < 4; i++)
#pragma unroll
                for (int j = 0; j < 8; j++) acc[i][j] += a[i] * bv[j];
        }
    }

#pragma unroll
    for (int i = 0; i < 4; i++) {
        float inv = 1.f / l_i[i];
        __nv_bfloat162 hv[4], lv[4];
#pragma unroll
        for (int j = 0; j < 4; j++) {
            float v0 = acc[i][2 * j] * inv;
            float v1 = acc[i][2 * j + 1] * inv;
            __nv_bfloat16 h0 = __float2bfloat16(v0);
            __nv_bfloat16 h1 = __float2bfloat16(v1);
            hv[j] = __nv_bfloat162(h0, h1);
            lv[j] = __nv_bfloat162(__float2bfloat16(v0 - __bfloat162float(h0)),
                                   __float2bfloat16(v1 - __bfloat162float(h1)));
        }
        size_t off = (((size_t)b * S_ + q0 + ty * 4 + i) * H_ + h) * D_ + tx * 8;
        *(uint4*)&Oh[off] = *(uint4*)hv;
        *(uint4*)&Ol[off] = *(uint4*)lv;
    }
}

// ---------------------------------------------------------------------------
extern "C" void kernel_launch(void* const* d_in, const int* in_sizes, int n_in,
                              void* d_out, int out_size)
{
    const float* x   = (const float*)d_in[0];
    const float* pe  = (const float*)d_in[1];
    const float* q_w = (const float*)d_in[2];
    const float* k_w = (const float*)d_in[3];
    const float* v_w = (const float*)d_in[4];
    const float* o_w = (const float*)d_in[5];
    const float* qnw = (const float*)d_in[6];
    const float* knw = (const float*)d_in[7];
    float* out = (float*)d_out;

    float *q, *k, *v;
    __nv_bfloat16 *xh, *xl, *qwh, *qwl, *kwh, *kwl, *vwh, *vwl, *owh, *owl, *ath, *atl;
    cudaGetSymbolAddress((void**)&q,   g_q);
    cudaGetSymbolAddress((void**)&k,   g_k);
    cudaGetSymbolAddress((void**)&v,   g_v);
    cudaGetSymbolAddress((void**)&xh,  g_xh);
    cudaGetSymbolAddress((void**)&xl,  g_xl);
    cudaGetSymbolAddress((void**)&qwh, g_qwh);
    cudaGetSymbolAddress((void**)&qwl, g_qwl);
    cudaGetSymbolAddress((void**)&kwh, g_kwh);
    cudaGetSymbolAddress((void**)&kwl, g_kwl);
    cudaGetSymbolAddress((void**)&vwh, g_vwh);
    cudaGetSymbolAddress((void**)&vwl, g_vwl);
    cudaGetSymbolAddress((void**)&owh, g_owh);
    cudaGetSymbolAddress((void**)&owl, g_owl);
    cudaGetSymbolAddress((void**)&ath, g_ath);
    cudaGetSymbolAddress((void**)&atl, g_atl);

    cudaFuncSetAttribute(flash_attn, cudaFuncAttributeMaxDynamicSharedMemorySize,
                         FLASH_SMEM);
    cudaFuncSetAttribute(gemm_bf16x3, cudaFuncAttributeMaxDynamicSharedMemorySize,
                         GEMM_SMEM);

    // 1) bf16 hi/lo splits of x and weights
    const int nx  = MROWS * HID_ / 4;
    const int nqw = H_ * D_ * HID_ / 4;
    const int nkw = KV_ * D_ * HID_ / 4;
    split_bf16<<<(nx  + 255) / 256, 256>>>((const float4*)x,
        (__nv_bfloat162*)xh, (__nv_bfloat162*)xl, nx);
    split_bf16<<<(nqw + 255) / 256, 256>>>((const float4*)q_w,
        (__nv_bfloat162*)qwh, (__nv_bfloat162*)qwl, nqw);
    split_bf16<<<(nkw + 255) / 256, 256>>>((const float4*)k_w,
        (__nv_bfloat162*)kwh, (__nv_bfloat162*)kwl, nkw);
    split_bf16<<<(nkw + 255) / 256, 256>>>((const float4*)v_w,
        (__nv_bfloat162*)vwh, (__nv_bfloat162*)vwl, nkw);
    split_bf16<<<(nqw + 255) / 256, 256>>>((const float4*)o_w,
        (__nv_bfloat162*)owh, (__nv_bfloat162*)owl, nqw);

    // 2) Projections (bf16x3 mma.sync)
    gemm_bf16x3<<<dim3(16, 32), 256, GEMM_SMEM>>>(xh, xl, qwh, qwl, q, H_ * D_, HID_);
    gemm_bf16x3<<<dim3(8,  32), 256, GEMM_SMEM>>>(xh, xl, kwh, kwl, k, KV_ * D_, HID_);
    gemm_bf16x3<<<dim3(8,  32), 256, GEMM_SMEM>>>(xh, xl, vwh, vwl, v, KV_ * D_, HID_);

    // 3) Per-head RMSNorm + RoPE (in place, fp32)
    rmsnorm_rope<<<MROWS * H_,  128>>>(q, pe, qnw, H_);
    rmsnorm_rope<<<MROWS * KV_, 128>>>(k, pe, knw, KV_);

    // 4) Causal GQA flash attention (fp32); epilogue emits bf16 hi/lo of att
    flash_attn<<<dim3(S_ / 64, H_, B_), 256, FLASH_SMEM>>>(q, k, v, ath, atl);

    // 5) Output projection (bf16x3 mma.sync)
    gemm_bf16x3<<<dim3(16, 32), 256, GEMM_SMEM>>>(ath, atl, owh, owl, out, HID_, HID_);
}

// round 7
// speedup vs baseline: 2.8891x; 1.7339x over previous
#include <cuda_runtime.h>
#include <cuda_bf16.h>
#include <math.h>
#include <stdint.h>

#define B_   2
#define S_   2048
#define HID_ 2048
#define H_   16
#define KV_  8
#define D_   128
#define MROWS (B_ * S_)   // 4096

// ---------------------------------------------------------------------------
// Scratch (__device__ globals; allocation-free rule)
// ---------------------------------------------------------------------------
__device__ float g_q[(size_t)MROWS * H_ * D_];
__device__ float g_k[(size_t)MROWS * KV_ * D_];
__device__ float g_v[(size_t)MROWS * KV_ * D_];
__device__ __nv_bfloat16 g_qh2[(size_t)MROWS * H_ * D_];
__device__ __nv_bfloat16 g_ql2[(size_t)MROWS * H_ * D_];
__device__ __nv_bfloat16 g_kh2[(size_t)MROWS * KV_ * D_];
__device__ __nv_bfloat16 g_kl2[(size_t)MROWS * KV_ * D_];
__device__ __nv_bfloat16 g_vh2[(size_t)MROWS * KV_ * D_];
__device__ __nv_bfloat16 g_vl2[(size_t)MROWS * KV_ * D_];
__device__ __nv_bfloat16 g_xh[(size_t)MROWS * HID_];
__device__ __nv_bfloat16 g_xl[(size_t)MROWS * HID_];
__device__ __nv_bfloat16 g_qwh[(size_t)H_ * D_ * HID_];
__device__ __nv_bfloat16 g_qwl[(size_t)H_ * D_ * HID_];
__device__ __nv_bfloat16 g_kwh[(size_t)KV_ * D_ * HID_];
__device__ __nv_bfloat16 g_kwl[(size_t)KV_ * D_ * HID_];
__device__ __nv_bfloat16 g_vwh[(size_t)KV_ * D_ * HID_];
__device__ __nv_bfloat16 g_vwl[(size_t)KV_ * D_ * HID_];
__device__ __nv_bfloat16 g_owh[(size_t)HID_ * H_ * D_];
__device__ __nv_bfloat16 g_owl[(size_t)HID_ * H_ * D_];
__device__ __nv_bfloat16 g_ath[(size_t)MROWS * H_ * D_];
__device__ __nv_bfloat16 g_atl[(size_t)MROWS * H_ * D_];

// ---------------------------------------------------------------------------
// Helpers
// ---------------------------------------------------------------------------
__device__ __forceinline__ uint32_t smem_u32(const void* p) {
    uint32_t a;
    asm("{ .reg .u64 t; cvta.to.shared.u64 t, %1; cvt.u32.u64 %0, t; }"
        : "=r"(a) : "l"(p));
    return a;
}

__device__ __forceinline__ void cpasync16(uint32_t dst, const void* src) {
    asm volatile("cp.async.cg.shared.global [%0], [%1], 16;" :: "r"(dst), "l"(src));
}

#define LDSM_X4(r0, r1, r2, r3, addr)                                         \
    asm volatile("ldmatrix.sync.aligned.m8n8.x4.shared.b16 {%0,%1,%2,%3}, [%4];" \
                 : "=r"(r0), "=r"(r1), "=r"(r2), "=r"(r3) : "r"(addr))

#define LDSM_X4_T(r0, r1, r2, r3, addr)                                       \
    asm volatile("ldmatrix.sync.aligned.m8n8.x4.trans.shared.b16 {%0,%1,%2,%3}, [%4];" \
                 : "=r"(r0), "=r"(r1), "=r"(r2), "=r"(r3) : "r"(addr))

__device__ __forceinline__ void ldsm_x4(uint32_t& r0, uint32_t& r1,
                                        uint32_t& r2, uint32_t& r3, uint32_t addr) {
    LDSM_X4(r0, r1, r2, r3, addr);
}

__device__ __forceinline__ void mma_bf16(float* c, const uint32_t* a, const uint32_t* b) {
    asm volatile("mma.sync.aligned.m16n8k16.row.col.f32.bf16.bf16.f32 "
                 "{%0,%1,%2,%3}, {%4,%5,%6,%7}, {%8,%9}, {%0,%1,%2,%3};"
                 : "+f"(c[0]), "+f"(c[1]), "+f"(c[2]), "+f"(c[3])
                 : "r"(a[0]), "r"(a[1]), "r"(a[2]), "r"(a[3]),
                   "r"(b[0]), "r"(b[1]));
}
__device__ __forceinline__ void mma16816(float* c, const uint32_t* a,
                                         uint32_t b0, uint32_t b1) {
    asm volatile("mma.sync.aligned.m16n8k16.row.col.f32.bf16.bf16.f32 "
                 "{%0,%1,%2,%3}, {%4,%5,%6,%7}, {%8,%9}, {%0,%1,%2,%3};"
                 : "+f"(c[0]), "+f"(c[1]), "+f"(c[2]), "+f"(c[3])
                 : "r"(a[0]), "r"(a[1]), "r"(a[2]), "r"(a[3]), "r"(b0), "r"(b1));
}

// pack (a,b) fp32 -> bf16x2 hi and residual bf16x2 lo
__device__ __forceinline__ void pk(float a, float b, uint32_t& hi, uint32_t& lo) {
    __nv_bfloat16 ha = __float2bfloat16(a), hb = __float2bfloat16(b);
    __nv_bfloat16 la = __float2bfloat16(a - __bfloat162float(ha));
    __nv_bfloat16 lb = __float2bfloat16(b - __bfloat162float(hb));
    hi = ((uint32_t)*(uint16_t*)&hb << 16) | (uint32_t)*(uint16_t*)&ha;
    lo = ((uint32_t)*(uint16_t*)&lb << 16) | (uint32_t)*(uint16_t*)&la;
}

// ---------------------------------------------------------------------------
// split fp32 -> (bf16 hi, bf16 lo)
// ---------------------------------------------------------------------------
__global__ __launch_bounds__(256) void split_bf16(
    const float4* __restrict__ s, __nv_bfloat162* __restrict__ h,
    __nv_bfloat162* __restrict__ l, int n4)
{
    int i = blockIdx.x * 256 + threadIdx.x;
    if (i >= n4) return;
    float4 v = s[i];
    __nv_bfloat16 hx = __float2bfloat16(v.x);
    __nv_bfloat16 hy = __float2bfloat16(v.y);
    __nv_bfloat16 hz = __float2bfloat16(v.z);
    __nv_bfloat16 hw = __float2bfloat16(v.w);
    __nv_bfloat16 lx = __float2bfloat16(v.x - __bfloat162float(hx));
    __nv_bfloat16 ly = __float2bfloat16(v.y - __bfloat162float(hy));
    __nv_bfloat16 lz = __float2bfloat16(v.z - __bfloat162float(hz));
    __nv_bfloat16 lw = __float2bfloat16(v.w - __bfloat162float(hw));
    h[2 * i]     = __nv_bfloat162(hx, hy);
    h[2 * i + 1] = __nv_bfloat162(hz, hw);
    l[2 * i]     = __nv_bfloat162(lx, ly);
    l[2 * i + 1] = __nv_bfloat162(lz, lw);
}

// ---------------------------------------------------------------------------
// bf16x3 mma.sync GEMM (validated in R5): C[m,n] = sum_k A[m,k]*B[n,k]
// ---------------------------------------------------------------------------
#define GK_      32
#define RSTR_B   80u
#define TILE_B   (128u * RSTR_B)
#define STAGE_B  (4u * TILE_B)
#define GEMM_SMEM (2 * 40960)

__device__ __forceinline__ void g_fill(
    uint32_t dst, const __nv_bfloat16* Ah, const __nv_bfloat16* Al,
    const __nv_bfloat16* Bh, const __nv_bfloat16* Bl,
    int m0, int n0, int K, int k0, int tid)
{
#pragma unroll
    for (int i = 0; i < 8; i++) {
        int idx = tid + i * 256;
        int t   = idx >> 9;
        int rem = idx & 511;
        int r   = rem >> 2;
        int seg = rem & 3;
        const __nv_bfloat16* src;
        if      (t == 0) src = Ah + (size_t)(m0 + r) * K + k0 + seg * 8;
        else if (t == 1) src = Al + (size_t)(m0 + r) * K + k0 + seg * 8;
        else if (t == 2) src = Bh + (size_t)(n0 + r) * K + k0 + seg * 8;
        else             src = Bl + (size_t)(n0 + r) * K + k0 + seg * 8;
        uint32_t d = dst + (uint32_t)t * TILE_B + (uint32_t)r * RSTR_B + (uint32_t)seg * 16u;
        cpasync16(d, src);
    }
}

__global__ __launch_bounds__(256, 1) void gemm_bf16x3(
    const __nv_bfloat16* __restrict__ Ah, const __nv_bfloat16* __restrict__ Al,
    const __nv_bfloat16* __restrict__ Bh, const __nv_bfloat16* __restrict__ Bl,
    float* __restrict__ C, int N, int K)
{
    extern __shared__ __align__(128) char smem[];
    const uint32_t sb  = smem_u32(smem);
    const int tid  = threadIdx.x;
    const int wid  = tid >> 5, lane = tid & 31;
    const int m0   = blockIdx.y << 7, n0 = blockIdx.x << 7;
    const int wm   = (wid >> 2) << 6;
    const int wn   = (wid & 3)  << 5;

    const uint32_t aoff = (uint32_t)(wm + (lane & 15)) * RSTR_B + (uint32_t)((lane >> 4) * 16);
    const uint32_t boff = (uint32_t)(wn + ((lane >> 4) << 3) + (lane & 7)) * RSTR_B
                        + (uint32_t)(((lane >> 3) & 1) * 16);

    float acc[4][4][4];
#pragma unroll
    for (int mi = 0; mi < 4; mi++)
#pragma unroll
        for (int ni = 0; ni < 4; ni++)
#pragma unroll
            for (int r = 0; r < 4; r++) acc[mi][ni][r] = 0.f;

    g_fill(sb, Ah, Al, Bh, Bl, m0, n0, K, 0, tid);
    asm volatile("cp.async.commit_group;");

    const int nit = K / GK_;
    for (int it = 0; it < nit; ++it) {
        const int cur = it & 1;
        if (it + 1 < nit) {
            g_fill(sb + (uint32_t)(cur ^ 1) * STAGE_B, Ah, Al, Bh, Bl,
                   m0, n0, K, (it + 1) * GK_, tid);
            asm volatile("cp.async.commit_group;");
            asm volatile("cp.async.wait_group 1;");
        } else {
            asm volatile("cp.async.wait_group 0;");
        }
        __syncthreads();

        const uint32_t stg = sb + (uint32_t)cur * STAGE_B;
        const uint32_t sAh = stg;
        const uint32_t sAl = stg + TILE_B;
        const uint32_t sBh = stg + 2u * TILE_B;
        const uint32_t sBl = stg + 3u * TILE_B;

#pragma unroll
        for (int kh = 0; kh < 2; kh++) {
            const uint32_t kb = (uint32_t)kh * 32u;
            uint32_t ah[4][4], al[4][4], bh[4][2], bl[4][2];
#pragma unroll
            for (int mi = 0; mi < 4; mi++) {
                ldsm_x4(ah[mi][0], ah[mi][1], ah[mi][2], ah[mi][3],
                        sAh + aoff + (uint32_t)(mi * 16) * RSTR_B + kb);
                ldsm_x4(al[mi][0], al[mi][1], al[mi][2], al[mi][3],
                        sAl + aoff + (uint32_t)(mi * 16) * RSTR_B + kb);
            }
#pragma unroll
            for (int nt = 0; nt < 2; nt++) {
                uint32_t r0, r1, r2, r3;
                ldsm_x4(r0, r1, r2, r3, sBh + boff + (uint32_t)(nt * 16) * RSTR_B + kb);
                bh[nt * 2 + 0][0] = r0; bh[nt * 2 + 0][1] = r1;
                bh[nt * 2 + 1][0] = r2; bh[nt * 2 + 1][1] = r3;
                ldsm_x4(r0, r1, r2, r3, sBl + boff + (uint32_t)(nt * 16) * RSTR_B + kb);
                bl[nt * 2 + 0][0] = r0; bl[nt * 2 + 0][1] = r1;
                bl[nt * 2 + 1][0] = r2; bl[nt * 2 + 1][1] = r3;
            }
#pragma unroll
            for (int mi = 0; mi < 4; mi++)
#pragma unroll
                for (int ni = 0; ni < 4; ni++) {
                    mma_bf16(acc[mi][ni], ah[mi], bh[ni]);
                    mma_bf16(acc[mi][ni], ah[mi], bl[ni]);
                    mma_bf16(acc[mi][ni], al[mi], bh[ni]);
                }
        }
        __syncthreads();
    }

#pragma unroll
    for (int mi = 0; mi < 4; mi++) {
        const int row = m0 + wm + mi * 16 + (lane >> 2);
#pragma unroll
        for (int ni = 0; ni < 4; ni++) {
            const int col = n0 + wn + ni * 8 + (lane & 3) * 2;
            *(float2*)&C[(size_t)row * N + col] =
                make_float2(acc[mi][ni][0], acc[mi][ni][1]);
            *(float2*)&C[(size_t)(row + 8) * N + col] =
                make_float2(acc[mi][ni][2], acc[mi][ni][3]);
        }
    }
}

// ---------------------------------------------------------------------------
// Per-head RMSNorm + RoPE; fp32 in, bf16 hi/lo out.
// ---------------------------------------------------------------------------
__global__ __launch_bounds__(128) void rmsnorm_rope_b(
    const float* __restrict__ X, const float* __restrict__ pe,
    const float* __restrict__ w, int nheads,
    __nv_bfloat16* __restrict__ Xh, __nv_bfloat16* __restrict__ Xl)
{
    __shared__ float sv[128];
    __shared__ float wsum[4];
    const int row = blockIdx.x;
    const int t   = threadIdx.x;
    const int bs  = row / nheads;

    float v  = X[(size_t)row * 128 + t];
    float ss = v * v;
#pragma unroll
    for (int o = 16; o > 0; o >>= 1) ss += __shfl_xor_sync(0xffffffffu, ss, o);
    if ((t & 31) == 0) wsum[t >> 5] = ss;
    __syncthreads();
    float tot = wsum[0] + wsum[1] + wsum[2] + wsum[3];
    float r   = rsqrtf(tot * (1.f / 128.f) + 1e-6f);
    float xn  = v * r * w[t];
    sv[t] = xn;
    __syncthreads();

    int   d = (t < 64) ? t : (t - 64);
    float c = pe[(size_t)bs * 128 + d];
    float s = pe[(size_t)bs * 128 + 64 + d];
    float other = (t < 64) ? sv[t + 64] : sv[t - 64];
    float out   = (t < 64) ? (xn * c - other * s) : (other * s + xn * c);
    __nv_bfloat16 hi = __float2bfloat16(out);
    Xh[(size_t)row * 128 + t] = hi;
    Xl[(size_t)row * 128 + t] = __float2bfloat16(out - __bfloat162float(hi));
}

// ---------------------------------------------------------------------------
// Flash attention on tensor cores (bf16x3 both matmuls), causal GQA.
// BR=128 (8 warps x 16 rows), BC=64, double-buffered cp.async KV stages.
// ---------------------------------------------------------------------------
#define FSTR   272u
#define SQH_   0u
#define SQL_   34816u
#define FST0   69632u
#define FKH    0u
#define FKL    17408u
#define FVH    34816u
#define FVL    52224u
#define FSTGSZ 69632u
#define FLASH2_SMEM 208896

__global__ __launch_bounds__(256, 1) void flash_mma(
    const __nv_bfloat16* __restrict__ Qh, const __nv_bfloat16* __restrict__ Ql,
    const __nv_bfloat16* __restrict__ Kh, const __nv_bfloat16* __restrict__ Kl,
    const __nv_bfloat16* __restrict__ Vh, const __nv_bfloat16* __restrict__ Vl,
    __nv_bfloat16* __restrict__ Oh, __nv_bfloat16* __restrict__ Ol)
{
    extern __shared__ __align__(16) char smem[];
    const uint32_t sb = smem_u32(smem);
    const int tid = threadIdx.x, lane = tid & 31, w = tid >> 5;
    const int bx = gridDim.x - 1 - blockIdx.x;   // heavy diagonals first
    const int h = blockIdx.y, b = blockIdx.z, kvh = h >> 1;
    const int g = lane >> 2, tg = lane & 3;

    // ---- Q tile fill (128 rows x 128 cols, hi+lo) ----
    {
        const size_t qbase = (((size_t)b * S_ + (size_t)bx * 128) * H_ + h) * D_;
#pragma unroll
        for (int i = 0; i < 8; i++) {
            int idx = tid + i * 256;
            int r = idx >> 4, seg = idx & 15;
            size_t src = qbase + (size_t)r * (H_ * D_) + seg * 8;
            uint32_t dst = sb + (uint32_t)r * FSTR + (uint32_t)seg * 16u;
            cpasync16(dst + SQH_, Qh + src);
            cpasync16(dst + SQL_, Ql + src);
        }
    }
    asm volatile("cp.async.commit_group;");

    auto fillKV = [&](int stage, int kt) {
        const size_t kbase = (((size_t)b * S_ + (size_t)kt * 64) * KV_ + kvh) * D_;
        const uint32_t sdst = sb + FST0 + (uint32_t)stage * FSTGSZ;
#pragma unroll
        for (int i = 0; i < 4; i++) {
            int idx = tid + i * 256;
            int r = idx >> 4, seg = idx & 15;
            size_t src = kbase + (size_t)r * (KV_ * D_) + seg * 8;
            uint32_t dst = sdst + (uint32_t)r * FSTR + (uint32_t)seg * 16u;
            cpasync16(dst + FKH, Kh + src);
            cpasync16(dst + FKL, Kl + src);
            cpasync16(dst + FVH, Vh + src);
            cpasync16(dst + FVL, Vl + src);
        }
        asm volatile("cp.async.commit_group;");
    };

    float o[16][4];
#pragma unroll
    for (int i = 0; i < 16; i++)
#pragma unroll
        for (int j = 0; j < 4; j++) o[i][j] = 0.f;
    float m0 = -1e30f, m1 = -1e30f, l0 = 0.f, l1 = 0.f;

    const int qr0 = bx * 128 + w * 16 + g;
    const int ntiles = 2 * bx + 2;
    const float sca = 0.08838834764831845f;   // 1/sqrt(128)

    fillKV(0, 0);

    for (int kt = 0; kt < ntiles; kt++) {
        const int cur = kt & 1;
        if (kt + 1 < ntiles) {
            fillKV(cur ^ 1, kt + 1);
            asm volatile("cp.async.wait_group 1;");
        } else {
            asm volatile("cp.async.wait_group 0;");
        }
        __syncthreads();

        if (kt * 64 <= bx * 128 + w * 16 + 15) {   // warp has unmasked work
            const uint32_t stg = sb + FST0 + (uint32_t)cur * FSTGSZ;
            const uint32_t aQ  = sb + (uint32_t)(w * 16 + (lane & 15)) * FSTR
                               + (uint32_t)((lane >> 4) * 16);
            const uint32_t bK  = stg + (uint32_t)((((lane >> 4) << 3) + (lane & 7)) * FSTR)
                               + (uint32_t)(((lane >> 3) & 1) * 16);

            // ---- S = Q K^T (bf16x3) ----
            float sc[8][4];
#pragma unroll
            for (int i = 0; i < 8; i++)
#pragma unroll
                for (int j = 0; j < 4; j++) sc[i][j] = 0.f;

#pragma unroll
            for (int kb = 0; kb < 8; kb++) {
                uint32_t qh4[4], ql4[4];
                ldsm_x4(qh4[0], qh4[1], qh4[2], qh4[3], aQ + SQH_ + kb * 32);
                ldsm_x4(ql4[0], ql4[1], ql4[2], ql4[3], aQ + SQL_ + kb * 32);
#pragma unroll
                for (int nt = 0; nt < 4; nt++) {
                    uint32_t kh0, kh1, kh2, kh3, kl0, kl1, kl2, kl3;
                    ldsm_x4(kh0, kh1, kh2, kh3,
                            bK + FKH + (uint32_t)(nt * 16) * FSTR + kb * 32);
                    ldsm_x4(kl0, kl1, kl2, kl3,
                            bK + FKL + (uint32_t)(nt * 16) * FSTR + kb * 32);
                    mma16816(sc[2 * nt],     qh4, kh0, kh1);
                    mma16816(sc[2 * nt],     qh4, kl0, kl1);
                    mma16816(sc[2 * nt],     ql4, kh0, kh1);
                    mma16816(sc[2 * nt + 1], qh4, kh2, kh3);
                    mma16816(sc[2 * nt + 1], qh4, kl2, kl3);
                    mma16816(sc[2 * nt + 1], ql4, kh2, kh3);
                }
            }

            // ---- scale + causal mask ----
            const bool maskt = (kt * 64 + 63 > bx * 128 + w * 16);
            const int row0 = qr0, row1 = qr0 + 8, cb = kt * 64;
#pragma unroll
            for (int nt = 0; nt < 8; nt++) {
                int c0 = cb + nt * 8 + tg * 2;
                float v0 = sc[nt][0] * sca, v1 = sc[nt][1] * sca;
                float v2 = sc[nt][2] * sca, v3 = sc[nt][3] * sca;
                if (maskt) {
                    if (c0     > row0) v0 = -1e30f;
                    if (c0 + 1 > row0) v1 = -1e30f;
                    if (c0     > row1) v2 = -1e30f;
                    if (c0 + 1 > row1) v3 = -1e30f;
                }
                sc[nt][0] = v0; sc[nt][1] = v1; sc[nt][2] = v2; sc[nt][3] = v3;
            }

            // ---- online softmax ----
            float mx0 = -1e30f, mx1 = -1e30f;
#pragma unroll
            for (int nt = 0; nt < 8; nt++) {
                mx0 = fmaxf(mx0, fmaxf(sc[nt][0], sc[nt][1]));
                mx1 = fmaxf(mx1, fmaxf(sc[nt][2], sc[nt][3]));
            }
            mx0 = fmaxf(mx0, __shfl_xor_sync(0xffffffffu, mx0, 1));
            mx0 = fmaxf(mx0, __shfl_xor_sync(0xffffffffu, mx0, 2));
            mx1 = fmaxf(mx1, __shfl_xor_sync(0xffffffffu, mx1, 1));
            mx1 = fmaxf(mx1, __shfl_xor_sync(0xffffffffu, mx1, 2));
            const float mn0 = fmaxf(m0, mx0), mn1 = fmaxf(m1, mx1);

            float s0 = 0.f, s1 = 0.f;
#pragma unroll
            for (int nt = 0; nt < 8; nt++) {
                float p0 = __expf(sc[nt][0] - mn0); sc[nt][0] = p0; s0 += p0;
                float p1 = __expf(sc[nt][1] - mn0); sc[nt][1] = p1; s0 += p1;
                float p2 = __expf(sc[nt][2] - mn1); sc[nt][2] = p2; s1 += p2;
                float p3 = __expf(sc[nt][3] - mn1); sc[nt][3] = p3; s1 += p3;
            }
            s0 += __shfl_xor_sync(0xffffffffu, s0, 1);
            s0 += __shfl_xor_sync(0xffffffffu, s0, 2);
            s1 += __shfl_xor_sync(0xffffffffu, s1, 1);
            s1 += __shfl_xor_sync(0xffffffffu, s1, 2);

            const float al0 = __expf(m0 - mn0), al1 = __expf(m1 - mn1);
            m0 = mn0; m1 = mn1;
            l0 = l0 * al0 + s0;
            l1 = l1 * al1 + s1;
#pragma unroll
            for (int nt = 0; nt < 16; nt++) {
                o[nt][0] *= al0; o[nt][1] *= al0;
                o[nt][2] *= al1; o[nt][3] *= al1;
            }

            // ---- P -> bf16 hi/lo A-fragments (in-register remap) ----
            uint32_t ph[4][4], pl[4][4];
#pragma unroll
            for (int j = 0; j < 4; j++) {
                pk(sc[2 * j][0],     sc[2 * j][1],     ph[j][0], pl[j][0]);
                pk(sc[2 * j][2],     sc[2 * j][3],     ph[j][1], pl[j][1]);
                pk(sc[2 * j + 1][0], sc[2 * j + 1][1], ph[j][2], pl[j][2]);
                pk(sc[2 * j + 1][2], sc[2 * j + 1][3], ph[j][3], pl[j][3]);
            }

            // ---- O += P V (bf16x3, V via ldmatrix.trans) ----
#pragma unroll
            for (int ks = 0; ks < 4; ks++) {
                const uint32_t vrow = stg
                    + (uint32_t)((ks * 16 + ((lane >> 3) & 1) * 8 + (lane & 7)) * FSTR)
                    + (uint32_t)((lane >> 4) * 16);
#pragma unroll
                for (int ntp = 0; ntp < 8; ntp++) {
                    uint32_t vh0, vh1, vh2, vh3, vl0, vl1, vl2, vl3;
                    LDSM_X4_T(vh0, vh1, vh2, vh3, vrow + FVH + ntp * 32);
                    LDSM_X4_T(vl0, vl1, vl2, vl3, vrow + FVL + ntp * 32);
                    mma16816(o[2 * ntp],     ph[ks], vh0, vh1);
                    mma16816(o[2 * ntp],     ph[ks], vl0, vl1);
                    mma16816(o[2 * ntp],     pl[ks], vh0, vh1);
                    mma16816(o[2 * ntp + 1], ph[ks], vh2, vh3);
                    mma16816(o[2 * ntp + 1], ph[ks], vl2, vl3);
                    mma16816(o[2 * ntp + 1], pl[ks], vh2, vh3);
                }
            }
        }
        __syncthreads();
    }

    // ---- epilogue: normalize, split to bf16 hi/lo, store ----
    const float i0 = 1.f / l0, i1 = 1.f / l1;
    const size_t o0 = (((size_t)b * S_ + (size_t)qr0) * H_ + h) * D_;
    const size_t o1 = o0 + (size_t)8 * (H_ * D_);
#pragma unroll
    for (int nt = 0; nt < 16; nt++) {
        const int col = nt * 8 + tg * 2;
        uint32_t hi, lo;
        pk(o[nt][0] * i0, o[nt][1] * i0, hi, lo);
        *(uint32_t*)&Oh[o0 + col] = hi;
        *(uint32_t*)&Ol[o0 + col] = lo;
        pk(o[nt][2] * i1, o[nt][3] * i1, hi, lo);
        *(uint32_t*)&Oh[o1 + col] = hi;
        *(uint32_t*)&Ol[o1 + col] = lo;
    }
}

// ---------------------------------------------------------------------------
extern "C" void kernel_launch(void* const* d_in, const int* in_sizes, int n_in,
                              void* d_out, int out_size)
{
    const float* x   = (const float*)d_in[0];
    const float* pe  = (const float*)d_in[1];
    const float* q_w = (const float*)d_in[2];
    const float* k_w = (const float*)d_in[3];
    const float* v_w = (const float*)d_in[4];
    const float* o_w = (const float*)d_in[5];
    const float* qnw = (const float*)d_in[6];
    const float* knw = (const float*)d_in[7];
    float* out = (float*)d_out;

    float *q, *k, *v;
    __nv_bfloat16 *qh, *ql, *kh, *kl, *vh, *vl;
    __nv_bfloat16 *xh, *xl, *qwh, *qwl, *kwh, *kwl, *vwh, *vwl, *owh, *owl, *ath, *atl;
    cudaGetSymbolAddress((void**)&q,   g_q);
    cudaGetSymbolAddress((void**)&k,   g_k);
    cudaGetSymbolAddress((void**)&v,   g_v);
    cudaGetSymbolAddress((void**)&qh,  g_qh2);
    cudaGetSymbolAddress((void**)&ql,  g_ql2);
    cudaGetSymbolAddress((void**)&kh,  g_kh2);
    cudaGetSymbolAddress((void**)&kl,  g_kl2);
    cudaGetSymbolAddress((void**)&vh,  g_vh2);
    cudaGetSymbolAddress((void**)&vl,  g_vl2);
    cudaGetSymbolAddress((void**)&xh,  g_xh);
    cudaGetSymbolAddress((void**)&xl,  g_xl);
    cudaGetSymbolAddress((void**)&qwh, g_qwh);
    cudaGetSymbolAddress((void**)&qwl, g_qwl);
    cudaGetSymbolAddress((void**)&kwh, g_kwh);
    cudaGetSymbolAddress((void**)&kwl, g_kwl);
    cudaGetSymbolAddress((void**)&vwh, g_vwh);
    cudaGetSymbolAddress((void**)&vwl, g_vwl);
    cudaGetSymbolAddress((void**)&owh, g_owh);
    cudaGetSymbolAddress((void**)&owl, g_owl);
    cudaGetSymbolAddress((void**)&ath, g_ath);
    cudaGetSymbolAddress((void**)&atl, g_atl);

    cudaFuncSetAttribute(gemm_bf16x3, cudaFuncAttributeMaxDynamicSharedMemorySize,
                         GEMM_SMEM);
    cudaFuncSetAttribute(flash_mma, cudaFuncAttributeMaxDynamicSharedMemorySize,
                         FLASH2_SMEM);

    // 1) bf16 hi/lo splits of x and weights
    const int nx  = MROWS * HID_ / 4;
    const int nqw = H_ * D_ * HID_ / 4;
    const int nkw = KV_ * D_ * HID_ / 4;
    split_bf16<<<(nx  + 255) / 256, 256>>>((const float4*)x,
        (__nv_bfloat162*)xh, (__nv_bfloat162*)xl, nx);
    split_bf16<<<(nqw + 255) / 256, 256>>>((const float4*)q_w,
        (__nv_bfloat162*)qwh, (__nv_bfloat162*)qwl, nqw);
    split_bf16<<<(nkw + 255) / 256, 256>>>((const float4*)k_w,
        (__nv_bfloat162*)kwh, (__nv_bfloat162*)kwl, nkw);
    split_bf16<<<(nkw + 255) / 256, 256>>>((const float4*)v_w,
        (__nv_bfloat162*)vwh, (__nv_bfloat162*)vwl, nkw);
    split_bf16<<<(nqw + 255) / 256, 256>>>((const float4*)o_w,
        (__nv_bfloat162*)owh, (__nv_bfloat162*)owl, nqw);

    // 2) Projections (bf16x3 mma.sync)
    gemm_bf16x3<<<dim3(16, 32), 256, GEMM_SMEM>>>(xh, xl, qwh, qwl, q, H_ * D_, HID_);
    gemm_bf16x3<<<dim3(8,  32), 256, GEMM_SMEM>>>(xh, xl, kwh, kwl, k, KV_ * D_, HID_);
    gemm_bf16x3<<<dim3(8,  32), 256, GEMM_SMEM>>>(xh, xl, vwh, vwl, v, KV_ * D_, HID_);

    // 3) V split to bf16 hi/lo for tensor-core flash
    const int nv = MROWS * KV_ * D_ / 4;
    split_bf16<<<(nv + 255) / 256, 256>>>((const float4*)v,
        (__nv_bfloat162*)vh, (__nv_bfloat162*)vl, nv);

    // 4) Per-head RMSNorm + RoPE, output bf16 hi/lo
    rmsnorm_rope_b<<<MROWS * H_,  128>>>(q, pe, qnw, H_,  qh, ql);
    rmsnorm_rope_b<<<MROWS * KV_, 128>>>(k, pe, knw, KV_, kh, kl);

    // 5) Causal GQA flash attention on tensor cores
    flash_mma<<<dim3(S_ / 128, H_, B_), 256, FLASH2_SMEM>>>(
        qh, ql, kh, kl, vh, vl, ath, atl);

    // 6) Output projection (bf16x3 mma.sync)
    gemm_bf16x3<<<dim3(16, 32), 256, GEMM_SMEM>>>(ath, atl, owh, owl, out, HID_, HID_);
}

// round 8
// speedup vs baseline: 3.0253x; 1.0471x over previous
#include <cuda_runtime.h>
#include <cuda_bf16.h>
#include <math.h>
#include <stdint.h>

#define B_   2
#define S_   2048
#define HID_ 2048
#define H_   16
#define KV_  8
#define D_   128
#define MROWS (B_ * S_)   // 4096

// ---------------------------------------------------------------------------
// Scratch (__device__ globals; allocation-free rule)
// ---------------------------------------------------------------------------
__device__ float g_q[(size_t)MROWS * H_ * D_];
__device__ float g_k[(size_t)MROWS * KV_ * D_];
__device__ float g_v[(size_t)MROWS * KV_ * D_];
__device__ __nv_bfloat16 g_qh2[(size_t)MROWS * H_ * D_];
__device__ __nv_bfloat16 g_ql2[(size_t)MROWS * H_ * D_];
__device__ __nv_bfloat16 g_kh2[(size_t)MROWS * KV_ * D_];
__device__ __nv_bfloat16 g_kl2[(size_t)MROWS * KV_ * D_];
__device__ __nv_bfloat16 g_vh2[(size_t)MROWS * KV_ * D_];
__device__ __nv_bfloat16 g_vl2[(size_t)MROWS * KV_ * D_];
__device__ __nv_bfloat16 g_xh[(size_t)MROWS * HID_];
__device__ __nv_bfloat16 g_xl[(size_t)MROWS * HID_];
__device__ __nv_bfloat16 g_qwh[(size_t)H_ * D_ * HID_];
__device__ __nv_bfloat16 g_qwl[(size_t)H_ * D_ * HID_];
__device__ __nv_bfloat16 g_kwh[(size_t)KV_ * D_ * HID_];
__device__ __nv_bfloat16 g_kwl[(size_t)KV_ * D_ * HID_];
__device__ __nv_bfloat16 g_vwh[(size_t)KV_ * D_ * HID_];
__device__ __nv_bfloat16 g_vwl[(size_t)KV_ * D_ * HID_];
__device__ __nv_bfloat16 g_owh[(size_t)HID_ * H_ * D_];
__device__ __nv_bfloat16 g_owl[(size_t)HID_ * H_ * D_];
__device__ __nv_bfloat16 g_ath[(size_t)MROWS * H_ * D_];
__device__ __nv_bfloat16 g_atl[(size_t)MROWS * H_ * D_];

// ---------------------------------------------------------------------------
// Helpers
// ---------------------------------------------------------------------------
__device__ __forceinline__ uint32_t smem_u32(const void* p) {
    uint32_t a;
    asm("{ .reg .u64 t; cvta.to.shared.u64 t, %1; cvt.u32.u64 %0, t; }"
        : "=r"(a) : "l"(p));
    return a;
}

__device__ __forceinline__ void cpasync16(uint32_t dst, const void* src) {
    asm volatile("cp.async.cg.shared.global [%0], [%1], 16;" :: "r"(dst), "l"(src));
}

#define LDSM_X4(r0, r1, r2, r3, addr)                                         \
    asm volatile("ldmatrix.sync.aligned.m8n8.x4.shared.b16 {%0,%1,%2,%3}, [%4];" \
                 : "=r"(r0), "=r"(r1), "=r"(r2), "=r"(r3) : "r"(addr))

#define LDSM_X4_T(r0, r1, r2, r3, addr)                                       \
    asm volatile("ldmatrix.sync.aligned.m8n8.x4.trans.shared.b16 {%0,%1,%2,%3}, [%4];" \
                 : "=r"(r0), "=r"(r1), "=r"(r2), "=r"(r3) : "r"(addr))

__device__ __forceinline__ void ldsm_x4(uint32_t& r0, uint32_t& r1,
                                        uint32_t& r2, uint32_t& r3, uint32_t addr) {
    LDSM_X4(r0, r1, r2, r3, addr);
}

__device__ __forceinline__ void mma_bf16(float* c, const uint32_t* a, const uint32_t* b) {
    asm volatile("mma.sync.aligned.m16n8k16.row.col.f32.bf16.bf16.f32 "
                 "{%0,%1,%2,%3}, {%4,%5,%6,%7}, {%8,%9}, {%0,%1,%2,%3};"
                 : "+f"(c[0]), "+f"(c[1]), "+f"(c[2]), "+f"(c[3])
                 : "r"(a[0]), "r"(a[1]), "r"(a[2]), "r"(a[3]),
                   "r"(b[0]), "r"(b[1]));
}
__device__ __forceinline__ void mma16816(float* c, const uint32_t* a,
                                         uint32_t b0, uint32_t b1) {
    asm volatile("mma.sync.aligned.m16n8k16.row.col.f32.bf16.bf16.f32 "
                 "{%0,%1,%2,%3}, {%4,%5,%6,%7}, {%8,%9}, {%0,%1,%2,%3};"
                 : "+f"(c[0]), "+f"(c[1]), "+f"(c[2]), "+f"(c[3])
                 : "r"(a[0]), "r"(a[1]), "r"(a[2]), "r"(a[3]), "r"(b0), "r"(b1));
}

// pack (a,b) fp32 -> bf16x2 hi and residual bf16x2 lo
__device__ __forceinline__ void pk(float a, float b, uint32_t& hi, uint32_t& lo) {
    __nv_bfloat16 ha = __float2bfloat16(a), hb = __float2bfloat16(b);
    __nv_bfloat16 la = __float2bfloat16(a - __bfloat162float(ha));
    __nv_bfloat16 lb = __float2bfloat16(b - __bfloat162float(hb));
    hi = ((uint32_t)*(uint16_t*)&hb << 16) | (uint32_t)*(uint16_t*)&ha;
    lo = ((uint32_t)*(uint16_t*)&lb << 16) | (uint32_t)*(uint16_t*)&la;
}

// ---------------------------------------------------------------------------
// split fp32 -> (bf16 hi, bf16 lo)
// ---------------------------------------------------------------------------
__global__ __launch_bounds__(256) void split_bf16(
    const float4* __restrict__ s, __nv_bfloat162* __restrict__ h,
    __nv_bfloat162* __restrict__ l, int n4)
{
    int i = blockIdx.x * 256 + threadIdx.x;
    if (i >= n4) return;
    float4 v = s[i];
    __nv_bfloat16 hx = __float2bfloat16(v.x);
    __nv_bfloat16 hy = __float2bfloat16(v.y);
    __nv_bfloat16 hz = __float2bfloat16(v.z);
    __nv_bfloat16 hw = __float2bfloat16(v.w);
    __nv_bfloat16 lx = __float2bfloat16(v.x - __bfloat162float(hx));
    __nv_bfloat16 ly = __float2bfloat16(v.y - __bfloat162float(hy));
    __nv_bfloat16 lz = __float2bfloat16(v.z - __bfloat162float(hz));
    __nv_bfloat16 lw = __float2bfloat16(v.w - __bfloat162float(hw));
    h[2 * i]     = __nv_bfloat162(hx, hy);
    h[2 * i + 1] = __nv_bfloat162(hz, hw);
    l[2 * i]     = __nv_bfloat162(lx, ly);
    l[2 * i + 1] = __nv_bfloat162(lz, lw);
}

// ---------------------------------------------------------------------------
// bf16x3 mma.sync GEMM body (validated): C[m,n] = sum_k A[m,k]*B[n,k]
// ---------------------------------------------------------------------------
#define GK_      32
#define RSTR_B   80u
#define TILE_B   (128u * RSTR_B)
#define STAGE_B  (4u * TILE_B)
#define GEMM_SMEM (2 * 40960)

__device__ __forceinline__ void g_fill(
    uint32_t dst, const __nv_bfloat16* Ah, const __nv_bfloat16* Al,
    const __nv_bfloat16* Bh, const __nv_bfloat16* Bl,
    int m0, int n0, int K, int k0, int tid)
{
#pragma unroll
    for (int i = 0; i < 8; i++) {
        int idx = tid + i * 256;
        int t   = idx >> 9;
        int rem = idx & 511;
        int r   = rem >> 2;
        int seg = rem & 3;
        const __nv_bfloat16* src;
        if      (t == 0) src = Ah + (size_t)(m0 + r) * K + k0 + seg * 8;
        else if (t == 1) src = Al + (size_t)(m0 + r) * K + k0 + seg * 8;
        else if (t == 2) src = Bh + (size_t)(n0 + r) * K + k0 + seg * 8;
        else             src = Bl + (size_t)(n0 + r) * K + k0 + seg * 8;
        uint32_t d = dst + (uint32_t)t * TILE_B + (uint32_t)r * RSTR_B + (uint32_t)seg * 16u;
        cpasync16(d, src);
    }
}

__device__ __forceinline__ void gemm_body(
    const __nv_bfloat16* Ah, const __nv_bfloat16* Al,
    const __nv_bfloat16* Bh, const __nv_bfloat16* Bl,
    float* C, int N, int K, int m0, int n0, char* smem)
{
    const uint32_t sb  = smem_u32(smem);
    const int tid  = threadIdx.x;
    const int wid  = tid >> 5, lane = tid & 31;
    const int wm   = (wid >> 2) << 6;
    const int wn   = (wid & 3)  << 5;

    const uint32_t aoff = (uint32_t)(wm + (lane & 15)) * RSTR_B + (uint32_t)((lane >> 4) * 16);
    const uint32_t boff = (uint32_t)(wn + ((lane >> 4) << 3) + (lane & 7)) * RSTR_B
                        + (uint32_t)(((lane >> 3) & 1) * 16);

    float acc[4][4][4];
#pragma unroll
    for (int mi = 0; mi < 4; mi++)
#pragma unroll
        for (int ni = 0; ni < 4; ni++)
#pragma unroll
            for (int r = 0; r < 4; r++) acc[mi][ni][r] = 0.f;

    g_fill(sb, Ah, Al, Bh, Bl, m0, n0, K, 0, tid);
    asm volatile("cp.async.commit_group;");

    const int nit = K / GK_;
    for (int it = 0; it < nit; ++it) {
        const int cur = it & 1;
        if (it + 1 < nit) {
            g_fill(sb + (uint32_t)(cur ^ 1) * STAGE_B, Ah, Al, Bh, Bl,
                   m0, n0, K, (it + 1) * GK_, tid);
            asm volatile("cp.async.commit_group;");
            asm volatile("cp.async.wait_group 1;");
        } else {
            asm volatile("cp.async.wait_group 0;");
        }
        __syncthreads();

        const uint32_t stg = sb + (uint32_t)cur * STAGE_B;
        const uint32_t sAh = stg;
        const uint32_t sAl = stg + TILE_B;
        const uint32_t sBh = stg + 2u * TILE_B;
        const uint32_t sBl = stg + 3u * TILE_B;

#pragma unroll
        for (int kh = 0; kh < 2; kh++) {
            const uint32_t kb = (uint32_t)kh * 32u;
            uint32_t ah[4][4], al[4][4], bh[4][2], bl[4][2];
#pragma unroll
            for (int mi = 0; mi < 4; mi++) {
                ldsm_x4(ah[mi][0], ah[mi][1], ah[mi][2], ah[mi][3],
                        sAh + aoff + (uint32_t)(mi * 16) * RSTR_B + kb);
                ldsm_x4(al[mi][0], al[mi][1], al[mi][2], al[mi][3],
                        sAl + aoff + (uint32_t)(mi * 16) * RSTR_B + kb);
            }
#pragma unroll
            for (int nt = 0; nt < 2; nt++) {
                uint32_t r0, r1, r2, r3;
                ldsm_x4(r0, r1, r2, r3, sBh + boff + (uint32_t)(nt * 16) * RSTR_B + kb);
                bh[nt * 2 + 0][0] = r0; bh[nt * 2 + 0][1] = r1;
                bh[nt * 2 + 1][0] = r2; bh[nt * 2 + 1][1] = r3;
                ldsm_x4(r0, r1, r2, r3, sBl + boff + (uint32_t)(nt * 16) * RSTR_B + kb);
                bl[nt * 2 + 0][0] = r0; bl[nt * 2 + 0][1] = r1;
                bl[nt * 2 + 1][0] = r2; bl[nt * 2 + 1][1] = r3;
            }
#pragma unroll
            for (int mi = 0; mi < 4; mi++)
#pragma unroll
                for (int ni = 0; ni < 4; ni++) {
                    mma_bf16(acc[mi][ni], ah[mi], bh[ni]);
                    mma_bf16(acc[mi][ni], ah[mi], bl[ni]);
                    mma_bf16(acc[mi][ni], al[mi], bh[ni]);
                }
        }
        __syncthreads();
    }

#pragma unroll
    for (int mi = 0; mi < 4; mi++) {
        const int row = m0 + wm + mi * 16 + (lane >> 2);
#pragma unroll
        for (int ni = 0; ni < 4; ni++) {
            const int col = n0 + wn + ni * 8 + (lane & 3) * 2;
            *(float2*)&C[(size_t)row * N + col] =
                make_float2(acc[mi][ni][0], acc[mi][ni][1]);
            *(float2*)&C[(size_t)(row + 8) * N + col] =
                make_float2(acc[mi][ni][2], acc[mi][ni][3]);
        }
    }
}

__global__ __launch_bounds__(256, 1) void gemm_bf16x3(
    const __nv_bfloat16* __restrict__ Ah, const __nv_bfloat16* __restrict__ Al,
    const __nv_bfloat16* __restrict__ Bh, const __nv_bfloat16* __restrict__ Bl,
    float* __restrict__ C, int N, int K)
{
    extern __shared__ __align__(128) char smem[];
    gemm_body(Ah, Al, Bh, Bl, C, N, K, blockIdx.y << 7, blockIdx.x << 7, smem);
}

// Fused Q/K/V projection: one launch, per-block weight/output select.
__global__ __launch_bounds__(256, 1) void gemm_qkv(
    const __nv_bfloat16* __restrict__ xh, const __nv_bfloat16* __restrict__ xl,
    const __nv_bfloat16* __restrict__ qwh, const __nv_bfloat16* __restrict__ qwl,
    const __nv_bfloat16* __restrict__ kwh, const __nv_bfloat16* __restrict__ kwl,
    const __nv_bfloat16* __restrict__ vwh, const __nv_bfloat16* __restrict__ vwl,
    float* __restrict__ q, float* __restrict__ k, float* __restrict__ v, int K)
{
    extern __shared__ __align__(128) char smem[];
    const int bxx = blockIdx.x;
    const __nv_bfloat16 *Bh, *Bl;
    float* C; int N, n0;
    if (bxx < 16)      { Bh = qwh; Bl = qwl; C = q; N = 2048; n0 = bxx << 7; }
    else if (bxx < 24) { Bh = kwh; Bl = kwl; C = k; N = 1024; n0 = (bxx - 16) << 7; }
    else               { Bh = vwh; Bl = vwl; C = v; N = 1024; n0 = (bxx - 24) << 7; }
    gemm_body(xh, xl, Bh, Bl, C, N, K, blockIdx.y << 7, n0, smem);
}

// ---------------------------------------------------------------------------
// Per-head RMSNorm + RoPE; fp32 in, bf16 hi/lo out.
// ---------------------------------------------------------------------------
__global__ __launch_bounds__(128) void rmsnorm_rope_b(
    const float* __restrict__ X, const float* __restrict__ pe,
    const float* __restrict__ w, int nheads,
    __nv_bfloat16* __restrict__ Xh, __nv_bfloat16* __restrict__ Xl)
{
    __shared__ float sv[128];
    __shared__ float wsum[4];
    const int row = blockIdx.x;
    const int t   = threadIdx.x;
    const int bs  = row / nheads;

    float v  = X[(size_t)row * 128 + t];
    float ss = v * v;
#pragma unroll
    for (int o = 16; o > 0; o >>= 1) ss += __shfl_xor_sync(0xffffffffu, ss, o);
    if ((t & 31) == 0) wsum[t >> 5] = ss;
    __syncthreads();
    float tot = wsum[0] + wsum[1] + wsum[2] + wsum[3];
    float r   = rsqrtf(tot * (1.f / 128.f) + 1e-6f);
    float xn  = v * r * w[t];
    sv[t] = xn;
    __syncthreads();

    int   d = (t < 64) ? t : (t - 64);
    float c = pe[(size_t)bs * 128 + d];
    float s = pe[(size_t)bs * 128 + 64 + d];
    float other = (t < 64) ? sv[t + 64] : sv[t - 64];
    float out   = (t < 64) ? (xn * c - other * s) : (other * s + xn * c);
    __nv_bfloat16 hi = __float2bfloat16(out);
    Xh[(size_t)row * 128 + t] = hi;
    Xl[(size_t)row * 128 + t] = __float2bfloat16(out - __bfloat162float(hi));
}

// ---------------------------------------------------------------------------
// Flash attention on tensor cores (bf16x3 both matmuls), causal GQA.
// BR=128 (8 warps x 16 rows), BC=64, double-buffered cp.async KV stages.
// exp2 domain softmax; exp/pack/PV interleaved per 16-col slice.
// ---------------------------------------------------------------------------
#define FSTR   272u
#define SQH_   0u
#define SQL_   34816u
#define FST0   69632u
#define FKH    0u
#define FKL    17408u
#define FVH    34816u
#define FVL    52224u
#define FSTGSZ 69632u
#define FLASH2_SMEM 208896

__global__ __launch_bounds__(256, 1) void flash_mma(
    const __nv_bfloat16* __restrict__ Qh, const __nv_bfloat16* __restrict__ Ql,
    const __nv_bfloat16* __restrict__ Kh, const __nv_bfloat16* __restrict__ Kl,
    const __nv_bfloat16* __restrict__ Vh, const __nv_bfloat16* __restrict__ Vl,
    __nv_bfloat16* __restrict__ Oh, __nv_bfloat16* __restrict__ Ol)
{
    extern __shared__ __align__(16) char smem[];
    const uint32_t sb = smem_u32(smem);
    const int tid = threadIdx.x, lane = tid & 31, w = tid >> 5;
    const int bx = gridDim.x - 1 - blockIdx.x;   // heavy diagonals first
    const int h = blockIdx.y, b = blockIdx.z, kvh = h >> 1;
    const int g = lane >> 2, tg = lane & 3;

    // ---- Q tile fill (128 rows x 128 cols, hi+lo) ----
    {
        const size_t qbase = (((size_t)b * S_ + (size_t)bx * 128) * H_ + h) * D_;
#pragma unroll
        for (int i = 0; i < 8; i++) {
            int idx = tid + i * 256;
            int r = idx >> 4, seg = idx & 15;
            size_t src = qbase + (size_t)r * (H_ * D_) + seg * 8;
            uint32_t dst = sb + (uint32_t)r * FSTR + (uint32_t)seg * 16u;
            cpasync16(dst + SQH_, Qh + src);
            cpasync16(dst + SQL_, Ql + src);
        }
    }
    asm volatile("cp.async.commit_group;");

    auto fillKV = [&](int stage, int kt) {
        const size_t kbase = (((size_t)b * S_ + (size_t)kt * 64) * KV_ + kvh) * D_;
        const uint32_t sdst = sb + FST0 + (uint32_t)stage * FSTGSZ;
#pragma unroll
        for (int i = 0; i < 4; i++) {
            int idx = tid + i * 256;
            int r = idx >> 4, seg = idx & 15;
            size_t src = kbase + (size_t)r * (KV_ * D_) + seg * 8;
            uint32_t dst = sdst + (uint32_t)r * FSTR + (uint32_t)seg * 16u;
            cpasync16(dst + FKH, Kh + src);
            cpasync16(dst + FKL, Kl + src);
            cpasync16(dst + FVH, Vh + src);
            cpasync16(dst + FVL, Vl + src);
        }
        asm volatile("cp.async.commit_group;");
    };

    float o[16][4];
#pragma unroll
    for (int i = 0; i < 16; i++)
#pragma unroll
        for (int j = 0; j < 4; j++) o[i][j] = 0.f;
    float m0 = -1e30f, m1 = -1e30f, l0 = 0.f, l1 = 0.f;

    const int qr0 = bx * 128 + w * 16 + g;
    const int ntiles = 2 * bx + 2;
    const float sca2 = 0.12751744f;   // log2(e)/sqrt(128)

    fillKV(0, 0);

    for (int kt = 0; kt < ntiles; kt++) {
        const int cur = kt & 1;
        if (kt + 1 < ntiles) {
            fillKV(cur ^ 1, kt + 1);
            asm volatile("cp.async.wait_group 1;");
        } else {
            asm volatile("cp.async.wait_group 0;");
        }
        __syncthreads();

        if (kt * 64 <= bx * 128 + w * 16 + 15) {   // warp has unmasked work
            const uint32_t stg = sb + FST0 + (uint32_t)cur * FSTGSZ;
            const uint32_t aQ  = sb + (uint32_t)(w * 16 + (lane & 15)) * FSTR
                               + (uint32_t)((lane >> 4) * 16);
            const uint32_t bK  = stg + (uint32_t)((((lane >> 4) << 3) + (lane & 7)) * FSTR)
                               + (uint32_t)(((lane >> 3) & 1) * 16);

            // ---- S = Q K^T (bf16x3) ----
            float sc[8][4];
#pragma unroll
            for (int i = 0; i < 8; i++)
#pragma unroll
                for (int j = 0; j < 4; j++) sc[i][j] = 0.f;

#pragma unroll
            for (int kb = 0; kb < 8; kb++) {
                uint32_t qh4[4], ql4[4];
                ldsm_x4(qh4[0], qh4[1], qh4[2], qh4[3], aQ + SQH_ + kb * 32);
                ldsm_x4(ql4[0], ql4[1], ql4[2], ql4[3], aQ + SQL_ + kb * 32);
#pragma unroll
                for (int nt = 0; nt < 4; nt++) {
                    uint32_t kh0, kh1, kh2, kh3, kl0, kl1, kl2, kl3;
                    ldsm_x4(kh0, kh1, kh2, kh3,
                            bK + FKH + (uint32_t)(nt * 16) * FSTR + kb * 32);
                    ldsm_x4(kl0, kl1, kl2, kl3,
                            bK + FKL + (uint32_t)(nt * 16) * FSTR + kb * 32);
                    mma16816(sc[2 * nt],     qh4, kh0, kh1);
                    mma16816(sc[2 * nt],     qh4, kl0, kl1);
                    mma16816(sc[2 * nt],     ql4, kh0, kh1);
                    mma16816(sc[2 * nt + 1], qh4, kh2, kh3);
                    mma16816(sc[2 * nt + 1], qh4, kl2, kl3);
                    mma16816(sc[2 * nt + 1], ql4, kh2, kh3);
                }
            }

            // ---- scale (log2 domain) + causal mask ----
            const bool maskt = (kt * 64 + 63 > bx * 128 + w * 16);
            const int row0 = qr0, row1 = qr0 + 8, cb = kt * 64;
#pragma unroll
            for (int nt = 0; nt < 8; nt++) {
                int c0 = cb + nt * 8 + tg * 2;
                float v0 = sc[nt][0] * sca2, v1 = sc[nt][1] * sca2;
                float v2 = sc[nt][2] * sca2, v3 = sc[nt][3] * sca2;
                if (maskt) {
                    if (c0     > row0) v0 = -1e30f;
                    if (c0 + 1 > row0) v1 = -1e30f;
                    if (c0     > row1) v2 = -1e30f;
                    if (c0 + 1 > row1) v3 = -1e30f;
                }
                sc[nt][0] = v0; sc[nt][1] = v1; sc[nt][2] = v2; sc[nt][3] = v3;
            }

            // ---- row max ----
            float mx0 = -1e30f, mx1 = -1e30f;
#pragma unroll
            for (int nt = 0; nt < 8; nt++) {
                mx0 = fmaxf(mx0, fmaxf(sc[nt][0], sc[nt][1]));
                mx1 = fmaxf(mx1, fmaxf(sc[nt][2], sc[nt][3]));
            }
            mx0 = fmaxf(mx0, __shfl_xor_sync(0xffffffffu, mx0, 1));
            mx0 = fmaxf(mx0, __shfl_xor_sync(0xffffffffu, mx0, 2));
            mx1 = fmaxf(mx1, __shfl_xor_sync(0xffffffffu, mx1, 1));
            mx1 = fmaxf(mx1, __shfl_xor_sync(0xffffffffu, mx1, 2));
            const float mn0 = fmaxf(m0, mx0), mn1 = fmaxf(m1, mx1);
            const float al0 = exp2f(m0 - mn0), al1 = exp2f(m1 - mn1);
            m0 = mn0; m1 = mn1;
#pragma unroll
            for (int nt = 0; nt < 16; nt++) {
                o[nt][0] *= al0; o[nt][1] *= al0;
                o[nt][2] *= al1; o[nt][3] *= al1;
            }

            // ---- per-slice: exp2 -> pack -> PV (interleaved) ----
            float s0 = 0.f, s1 = 0.f;
#pragma unroll
            for (int j = 0; j < 4; j++) {
                float p00 = exp2f(sc[2 * j][0] - mn0);
                float p01 = exp2f(sc[2 * j][1] - mn0);
                float p02 = exp2f(sc[2 * j][2] - mn1);
                float p03 = exp2f(sc[2 * j][3] - mn1);
                float p10 = exp2f(sc[2 * j + 1][0] - mn0);
                float p11 = exp2f(sc[2 * j + 1][1] - mn0);
                float p12 = exp2f(sc[2 * j + 1][2] - mn1);
                float p13 = exp2f(sc[2 * j + 1][3] - mn1);
                s0 += (p00 + p01) + (p10 + p11);
                s1 += (p02 + p03) + (p12 + p13);

                uint32_t ph[4], pl[4];
                pk(p00, p01, ph[0], pl[0]);
                pk(p02, p03, ph[1], pl[1]);
                pk(p10, p11, ph[2], pl[2]);
                pk(p12, p13, ph[3], pl[3]);

                const uint32_t vrow = stg
                    + (uint32_t)((j * 16 + ((lane >> 3) & 1) * 8 + (lane & 7)) * FSTR)
                    + (uint32_t)((lane >> 4) * 16);
#pragma unroll
                for (int ntp = 0; ntp < 8; ntp++) {
                    uint32_t vh0, vh1, vh2, vh3, vl0, vl1, vl2, vl3;
                    LDSM_X4_T(vh0, vh1, vh2, vh3, vrow + FVH + ntp * 32);
                    LDSM_X4_T(vl0, vl1, vl2, vl3, vrow + FVL + ntp * 32);
                    mma16816(o[2 * ntp],     ph, vh0, vh1);
                    mma16816(o[2 * ntp],     ph, vl0, vl1);
                    mma16816(o[2 * ntp],     pl, vh0, vh1);
                    mma16816(o[2 * ntp + 1], ph, vh2, vh3);
                    mma16816(o[2 * ntp + 1], ph, vl2, vl3);
                    mma16816(o[2 * ntp + 1], pl, vh2, vh3);
                }
            }
            s0 += __shfl_xor_sync(0xffffffffu, s0, 1);
            s0 += __shfl_xor_sync(0xffffffffu, s0, 2);
            s1 += __shfl_xor_sync(0xffffffffu, s1, 1);
            s1 += __shfl_xor_sync(0xffffffffu, s1, 2);
            l0 = l0 * al0 + s0;
            l1 = l1 * al1 + s1;
        }
        __syncthreads();
    }

    // ---- epilogue: normalize, split to bf16 hi/lo, store ----
    const float i0 = 1.f / l0, i1 = 1.f / l1;
    const size_t o0 = (((size_t)b * S_ + (size_t)qr0) * H_ + h) * D_;
    const size_t o1 = o0 + (size_t)8 * (H_ * D_);
#pragma unroll
    for (int nt = 0; nt < 16; nt++) {
        const int col = nt * 8 + tg * 2;
        uint32_t hi, lo;
        pk(o[nt][0] * i0, o[nt][1] * i0, hi, lo);
        *(uint32_t*)&Oh[o0 + col] = hi;
        *(uint32_t*)&Ol[o0 + col] = lo;
        pk(o[nt][2] * i1, o[nt][3] * i1, hi, lo);
        *(uint32_t*)&Oh[o1 + col] = hi;
        *(uint32_t*)&Ol[o1 + col] = lo;
    }
}

// ---------------------------------------------------------------------------
extern "C" void kernel_launch(void* const* d_in, const int* in_sizes, int n_in,
                              void* d_out, int out_size)
{
    const float* x   = (const float*)d_in[0];
    const float* pe  = (const float*)d_in[1];
    const float* q_w = (const float*)d_in[2];
    const float* k_w = (const float*)d_in[3];
    const float* v_w = (const float*)d_in[4];
    const float* o_w = (const float*)d_in[5];
    const float* qnw = (const float*)d_in[6];
    const float* knw = (const float*)d_in[7];
    float* out = (float*)d_out;

    float *q, *k, *v;
    __nv_bfloat16 *qh, *ql, *kh, *kl, *vh, *vl;
    __nv_bfloat16 *xh, *xl, *qwh, *qwl, *kwh, *kwl, *vwh, *vwl, *owh, *owl, *ath, *atl;
    cudaGetSymbolAddress((void**)&q,   g_q);
    cudaGetSymbolAddress((void**)&k,   g_k);
    cudaGetSymbolAddress((void**)&v,   g_v);
    cudaGetSymbolAddress((void**)&qh,  g_qh2);
    cudaGetSymbolAddress((void**)&ql,  g_ql2);
    cudaGetSymbolAddress((void**)&kh,  g_kh2);
    cudaGetSymbolAddress((void**)&kl,  g_kl2);
    cudaGetSymbolAddress((void**)&vh,  g_vh2);
    cudaGetSymbolAddress((void**)&vl,  g_vl2);
    cudaGetSymbolAddress((void**)&xh,  g_xh);
    cudaGetSymbolAddress((void**)&xl,  g_xl);
    cudaGetSymbolAddress((void**)&qwh, g_qwh);
    cudaGetSymbolAddress((void**)&qwl, g_qwl);
    cudaGetSymbolAddress((void**)&kwh, g_kwh);
    cudaGetSymbolAddress((void**)&kwl, g_kwl);
    cudaGetSymbolAddress((void**)&vwh, g_vwh);
    cudaGetSymbolAddress((void**)&vwl, g_vwl);
    cudaGetSymbolAddress((void**)&owh, g_owh);
    cudaGetSymbolAddress((void**)&owl, g_owl);
    cudaGetSymbolAddress((void**)&ath, g_ath);
    cudaGetSymbolAddress((void**)&atl, g_atl);

    cudaFuncSetAttribute(gemm_bf16x3, cudaFuncAttributeMaxDynamicSharedMemorySize,
                         GEMM_SMEM);
    cudaFuncSetAttribute(gemm_qkv, cudaFuncAttributeMaxDynamicSharedMemorySize,
                         GEMM_SMEM);
    cudaFuncSetAttribute(flash_mma, cudaFuncAttributeMaxDynamicSharedMemorySize,
                         FLASH2_SMEM);

    // 1) bf16 hi/lo splits of x and weights
    const int nx  = MROWS * HID_ / 4;
    const int nqw = H_ * D_ * HID_ / 4;
    const int nkw = KV_ * D_ * HID_ / 4;
    split_bf16<<<(nx  + 255) / 256, 256>>>((const float4*)x,
        (__nv_bfloat162*)xh, (__nv_bfloat162*)xl, nx);
    split_bf16<<<(nqw + 255) / 256, 256>>>((const float4*)q_w,
        (__nv_bfloat162*)qwh, (__nv_bfloat162*)qwl, nqw);
    split_bf16<<<(nkw + 255) / 256, 256>>>((const float4*)k_w,
        (__nv_bfloat162*)kwh, (__nv_bfloat162*)kwl, nkw);
    split_bf16<<<(nkw + 255) / 256, 256>>>((const float4*)v_w,
        (__nv_bfloat162*)vwh, (__nv_bfloat162*)vwl, nkw);
    split_bf16<<<(nqw + 255) / 256, 256>>>((const float4*)o_w,
        (__nv_bfloat162*)owh, (__nv_bfloat162*)owl, nqw);

    // 2) Fused Q/K/V projections (bf16x3 mma.sync, one launch)
    gemm_qkv<<<dim3(32, 32), 256, GEMM_SMEM>>>(xh, xl, qwh, qwl, kwh, kwl,
                                               vwh, vwl, q, k, v, HID_);

    // 3) V split to bf16 hi/lo for tensor-core flash
    const int nv = MROWS * KV_ * D_ / 4;
    split_bf16<<<(nv + 255) / 256, 256>>>((const float4*)v,
        (__nv_bfloat162*)vh, (__nv_bfloat162*)vl, nv);

    // 4) Per-head RMSNorm + RoPE, output bf16 hi/lo
    rmsnorm_rope_b<<<MROWS * H_,  128>>>(q, pe, qnw, H_,  qh, ql);
    rmsnorm_rope_b<<<MROWS * KV_, 128>>>(k, pe, knw, KV_, kh, kl);

    // 5) Causal GQA flash attention on tensor cores
    flash_mma<<<dim3(S_ / 128, H_, B_), 256, FLASH2_SMEM>>>(
        qh, ql, kh, kl, vh, vl, ath, atl);

    // 6) Output projection (bf16x3 mma.sync)
    gemm_bf16x3<<<dim3(16, 32), 256, GEMM_SMEM>>>(ath, atl, owh, owl, out, HID_, HID_);
}

// round 10
// speedup vs baseline: 3.0425x; 1.0057x over previous
#include <cuda_runtime.h>
#include <cuda_bf16.h>
#include <math.h>
#include <stdint.h>

#define B_   2
#define S_   2048
#define HID_ 2048
#define H_   16
#define KV_  8
#define D_   128
#define MROWS (B_ * S_)   // 4096

// ---------------------------------------------------------------------------
// Scratch (__device__ globals; allocation-free rule)
// ---------------------------------------------------------------------------
__device__ float g_q[(size_t)MROWS * H_ * D_];
__device__ float g_k[(size_t)MROWS * KV_ * D_];
__device__ float g_v[(size_t)MROWS * KV_ * D_];
__device__ __nv_bfloat16 g_qh2[(size_t)MROWS * H_ * D_];
__device__ __nv_bfloat16 g_ql2[(size_t)MROWS * H_ * D_];
__device__ __nv_bfloat16 g_kh2[(size_t)MROWS * KV_ * D_];
__device__ __nv_bfloat16 g_kl2[(size_t)MROWS * KV_ * D_];
__device__ __nv_bfloat16 g_vh2[(size_t)MROWS * KV_ * D_];
__device__ __nv_bfloat16 g_vl2[(size_t)MROWS * KV_ * D_];
__device__ __nv_bfloat16 g_xh[(size_t)MROWS * HID_];
__device__ __nv_bfloat16 g_xl[(size_t)MROWS * HID_];
__device__ __nv_bfloat16 g_qwh[(size_t)H_ * D_ * HID_];
__device__ __nv_bfloat16 g_qwl[(size_t)H_ * D_ * HID_];
__device__ __nv_bfloat16 g_kwh[(size_t)KV_ * D_ * HID_];
__device__ __nv_bfloat16 g_kwl[(size_t)KV_ * D_ * HID_];
__device__ __nv_bfloat16 g_vwh[(size_t)KV_ * D_ * HID_];
__device__ __nv_bfloat16 g_vwl[(size_t)KV_ * D_ * HID_];
__device__ __nv_bfloat16 g_owh[(size_t)HID_ * H_ * D_];
__device__ __nv_bfloat16 g_owl[(size_t)HID_ * H_ * D_];
__device__ __nv_bfloat16 g_ath[(size_t)MROWS * H_ * D_];
__device__ __nv_bfloat16 g_atl[(size_t)MROWS * H_ * D_];

// ---------------------------------------------------------------------------
// Helpers
// ---------------------------------------------------------------------------
__device__ __forceinline__ uint32_t smem_u32(const void* p) {
    uint32_t a;
    asm("{ .reg .u64 t; cvta.to.shared.u64 t, %1; cvt.u32.u64 %0, t; }"
        : "=r"(a) : "l"(p));
    return a;
}

__device__ __forceinline__ void cpasync16(uint32_t dst, const void* src) {
    asm volatile("cp.async.cg.shared.global [%0], [%1], 16;" :: "r"(dst), "l"(src));
}

#define LDSM_X4(r0, r1, r2, r3, addr)                                         \
    asm volatile("ldmatrix.sync.aligned.m8n8.x4.shared.b16 {%0,%1,%2,%3}, [%4];" \
                 : "=r"(r0), "=r"(r1), "=r"(r2), "=r"(r3) : "r"(addr))

#define LDSM_X4_T(r0, r1, r2, r3, addr)                                       \
    asm volatile("ldmatrix.sync.aligned.m8n8.x4.trans.shared.b16 {%0,%1,%2,%3}, [%4];" \
                 : "=r"(r0), "=r"(r1), "=r"(r2), "=r"(r3) : "r"(addr))

__device__ __forceinline__ void ldsm_x4(uint32_t& r0, uint32_t& r1,
                                        uint32_t& r2, uint32_t& r3, uint32_t addr) {
    LDSM_X4(r0, r1, r2, r3, addr);
}

__device__ __forceinline__ void mma_bf16(float* c, const uint32_t* a, const uint32_t* b) {
    asm volatile("mma.sync.aligned.m16n8k16.row.col.f32.bf16.bf16.f32 "
                 "{%0,%1,%2,%3}, {%4,%5,%6,%7}, {%8,%9}, {%0,%1,%2,%3};"
                 : "+f"(c[0]), "+f"(c[1]), "+f"(c[2]), "+f"(c[3])
                 : "r"(a[0]), "r"(a[1]), "r"(a[2]), "r"(a[3]),
                   "r"(b[0]), "r"(b[1]));
}
__device__ __forceinline__ void mma16816(float* c, const uint32_t* a,
                                         uint32_t b0, uint32_t b1) {
    asm volatile("mma.sync.aligned.m16n8k16.row.col.f32.bf16.bf16.f32 "
                 "{%0,%1,%2,%3}, {%4,%5,%6,%7}, {%8,%9}, {%0,%1,%2,%3};"
                 : "+f"(c[0]), "+f"(c[1]), "+f"(c[2]), "+f"(c[3])
                 : "r"(a[0]), "r"(a[1]), "r"(a[2]), "r"(a[3]), "r"(b0), "r"(b1));
}

// pack (a,b) fp32 -> bf16x2 hi and residual bf16x2 lo
__device__ __forceinline__ void pk(float a, float b, uint32_t& hi, uint32_t& lo) {
    __nv_bfloat16 ha = __float2bfloat16(a), hb = __float2bfloat16(b);
    __nv_bfloat16 la = __float2bfloat16(a - __bfloat162float(ha));
    __nv_bfloat16 lb = __float2bfloat16(b - __bfloat162float(hb));
    hi = ((uint32_t)*(uint16_t*)&hb << 16) | (uint32_t)*(uint16_t*)&ha;
    lo = ((uint32_t)*(uint16_t*)&lb << 16) | (uint32_t)*(uint16_t*)&la;
}

// ---------------------------------------------------------------------------
// split fp32 -> (bf16 hi, bf16 lo)
// ---------------------------------------------------------------------------
__global__ __launch_bounds__(256) void split_bf16(
    const float4* __restrict__ s, __nv_bfloat162* __restrict__ h,
    __nv_bfloat162* __restrict__ l, int n4)
{
    int i = blockIdx.x * 256 + threadIdx.x;
    if (i >= n4) return;
    float4 v = s[i];
    __nv_bfloat16 hx = __float2bfloat16(v.x);
    __nv_bfloat16 hy = __float2bfloat16(v.y);
    __nv_bfloat16 hz = __float2bfloat16(v.z);
    __nv_bfloat16 hw = __float2bfloat16(v.w);
    __nv_bfloat16 lx = __float2bfloat16(v.x - __bfloat162float(hx));
    __nv_bfloat16 ly = __float2bfloat16(v.y - __bfloat162float(hy));
    __nv_bfloat16 lz = __float2bfloat16(v.z - __bfloat162float(hz));
    __nv_bfloat16 lw = __float2bfloat16(v.w - __bfloat162float(hw));
    h[2 * i]     = __nv_bfloat162(hx, hy);
    h[2 * i + 1] = __nv_bfloat162(hz, hw);
    l[2 * i]     = __nv_bfloat162(lx, ly);
    l[2 * i + 1] = __nv_bfloat162(lz, lw);
}

// ---------------------------------------------------------------------------
// bf16x3 mma.sync GEMM body (validated): C[m,n] = sum_k A[m,k]*B[n,k]
// ---------------------------------------------------------------------------
#define GK_      32
#define RSTR_B   80u
#define TILE_B   (128u * RSTR_B)
#define STAGE_B  (4u * TILE_B)
#define GEMM_SMEM (2 * 40960)

__device__ __forceinline__ void g_fill(
    uint32_t dst, const __nv_bfloat16* Ah, const __nv_bfloat16* Al,
    const __nv_bfloat16* Bh, const __nv_bfloat16* Bl,
    int m0, int n0, int K, int k0, int tid)
{
#pragma unroll
    for (int i = 0; i < 8; i++) {
        int idx = tid + i * 256;
        int t   = idx >> 9;
        int rem = idx & 511;
        int r   = rem >> 2;
        int seg = rem & 3;
        const __nv_bfloat16* src;
        if      (t == 0) src = Ah + (size_t)(m0 + r) * K + k0 + seg * 8;
        else if (t == 1) src = Al + (size_t)(m0 + r) * K + k0 + seg * 8;
        else if (t == 2) src = Bh + (size_t)(n0 + r) * K + k0 + seg * 8;
        else             src = Bl + (size_t)(n0 + r) * K + k0 + seg * 8;
        uint32_t d = dst + (uint32_t)t * TILE_B + (uint32_t)r * RSTR_B + (uint32_t)seg * 16u;
        cpasync16(d, src);
    }
}

__device__ __forceinline__ void gemm_body(
    const __nv_bfloat16* Ah, const __nv_bfloat16* Al,
    const __nv_bfloat16* Bh, const __nv_bfloat16* Bl,
    float* C, int N, int K, int m0, int n0, char* smem)
{
    const uint32_t sb  = smem_u32(smem);
    const int tid  = threadIdx.x;
    const int wid  = tid >> 5, lane = tid & 31;
    const int wm   = (wid >> 2) << 6;
    const int wn   = (wid & 3)  << 5;

    const uint32_t aoff = (uint32_t)(wm + (lane & 15)) * RSTR_B + (uint32_t)((lane >> 4) * 16);
    const uint32_t boff = (uint32_t)(wn + ((lane >> 4) << 3) + (lane & 7)) * RSTR_B
                        + (uint32_t)(((lane >> 3) & 1) * 16);

    float acc[4][4][4];
#pragma unroll
    for (int mi = 0; mi < 4; mi++)
#pragma unroll
        for (int ni = 0; ni < 4; ni++)
#pragma unroll
            for (int r = 0; r < 4; r++) acc[mi][ni][r] = 0.f;

    g_fill(sb, Ah, Al, Bh, Bl, m0, n0, K, 0, tid);
    asm volatile("cp.async.commit_group;");

    const int nit = K / GK_;
    for (int it = 0; it < nit; ++it) {
        const int cur = it & 1;
        if (it + 1 < nit) {
            g_fill(sb + (uint32_t)(cur ^ 1) * STAGE_B, Ah, Al, Bh, Bl,
                   m0, n0, K, (it + 1) * GK_, tid);
            asm volatile("cp.async.commit_group;");
            asm volatile("cp.async.wait_group 1;");
        } else {
            asm volatile("cp.async.wait_group 0;");
        }
        __syncthreads();

        const uint32_t stg = sb + (uint32_t)cur * STAGE_B;
        const uint32_t sAh = stg;
        const uint32_t sAl = stg + TILE_B;
        const uint32_t sBh = stg + 2u * TILE_B;
        const uint32_t sBl = stg + 3u * TILE_B;

#pragma unroll
        for (int kh = 0; kh < 2; kh++) {
            const uint32_t kb = (uint32_t)kh * 32u;
            uint32_t ah[4][4], al[4][4], bh[4][2], bl[4][2];
#pragma unroll
            for (int mi = 0; mi < 4; mi++) {
                ldsm_x4(ah[mi][0], ah[mi][1], ah[mi][2], ah[mi][3],
                        sAh + aoff + (uint32_t)(mi * 16) * RSTR_B + kb);
                ldsm_x4(al[mi][0], al[mi][1], al[mi][2], al[mi][3],
                        sAl + aoff + (uint32_t)(mi * 16) * RSTR_B + kb);
            }
#pragma unroll
            for (int nt = 0; nt < 2; nt++) {
                uint32_t r0, r1, r2, r3;
                ldsm_x4(r0, r1, r2, r3, sBh + boff + (uint32_t)(nt * 16) * RSTR_B + kb);
                bh[nt * 2 + 0][0] = r0; bh[nt * 2 + 0][1] = r1;
                bh[nt * 2 + 1][0] = r2; bh[nt * 2 + 1][1] = r3;
                ldsm_x4(r0, r1, r2, r3, sBl + boff + (uint32_t)(nt * 16) * RSTR_B + kb);
                bl[nt * 2 + 0][0] = r0; bl[nt * 2 + 0][1] = r1;
                bl[nt * 2 + 1][0] = r2; bl[nt * 2 + 1][1] = r3;
            }
#pragma unroll
            for (int mi = 0; mi < 4; mi++)
#pragma unroll
                for (int ni = 0; ni < 4; ni++) {
                    mma_bf16(acc[mi][ni], ah[mi], bh[ni]);
                    mma_bf16(acc[mi][ni], ah[mi], bl[ni]);
                    mma_bf16(acc[mi][ni], al[mi], bh[ni]);
                }
        }
        __syncthreads();
    }

#pragma unroll
    for (int mi = 0; mi < 4; mi++) {
        const int row = m0 + wm + mi * 16 + (lane >> 2);
#pragma unroll
        for (int ni = 0; ni < 4; ni++) {
            const int col = n0 + wn + ni * 8 + (lane & 3) * 2;
            *(float2*)&C[(size_t)row * N + col] =
                make_float2(acc[mi][ni][0], acc[mi][ni][1]);
            *(float2*)&C[(size_t)(row + 8) * N + col] =
                make_float2(acc[mi][ni][2], acc[mi][ni][3]);
        }
    }
}

__global__ __launch_bounds__(256, 1) void gemm_bf16x3(
    const __nv_bfloat16* __restrict__ Ah, const __nv_bfloat16* __restrict__ Al,
    const __nv_bfloat16* __restrict__ Bh, const __nv_bfloat16* __restrict__ Bl,
    float* __restrict__ C, int N, int K)
{
    extern __shared__ __align__(128) char smem[];
    gemm_body(Ah, Al, Bh, Bl, C, N, K, blockIdx.y << 7, blockIdx.x << 7, smem);
}

// Fused Q/K/V projection: one launch, per-block weight/output select.
__global__ __launch_bounds__(256, 1) void gemm_qkv(
    const __nv_bfloat16* __restrict__ xh, const __nv_bfloat16* __restrict__ xl,
    const __nv_bfloat16* __restrict__ qwh, const __nv_bfloat16* __restrict__ qwl,
    const __nv_bfloat16* __restrict__ kwh, const __nv_bfloat16* __restrict__ kwl,
    const __nv_bfloat16* __restrict__ vwh, const __nv_bfloat16* __restrict__ vwl,
    float* __restrict__ q, float* __restrict__ k, float* __restrict__ v, int K)
{
    extern __shared__ __align__(128) char smem[];
    const int bxx = blockIdx.x;
    const __nv_bfloat16 *Bh, *Bl;
    float* C; int N, n0;
    if (bxx < 16)      { Bh = qwh; Bl = qwl; C = q; N = 2048; n0 = bxx << 7; }
    else if (bxx < 24) { Bh = kwh; Bl = kwl; C = k; N = 1024; n0 = (bxx - 16) << 7; }
    else               { Bh = vwh; Bl = vwl; C = v; N = 1024; n0 = (bxx - 24) << 7; }
    gemm_body(xh, xl, Bh, Bl, C, N, K, blockIdx.y << 7, n0, smem);
}

// ---------------------------------------------------------------------------
// Per-head RMSNorm + RoPE; fp32 in, bf16 hi/lo out.
// ---------------------------------------------------------------------------
__global__ __launch_bounds__(128) void rmsnorm_rope_b(
    const float* __restrict__ X, const float* __restrict__ pe,
    const float* __restrict__ w, int nheads,
    __nv_bfloat16* __restrict__ Xh, __nv_bfloat16* __restrict__ Xl)
{
    __shared__ float sv[128];
    __shared__ float wsum[4];
    const int row = blockIdx.x;
    const int t   = threadIdx.x;
    const int bs  = row / nheads;

    float v  = X[(size_t)row * 128 + t];
    float ss = v * v;
#pragma unroll
    for (int o = 16; o > 0; o >>= 1) ss += __shfl_xor_sync(0xffffffffu, ss, o);
    if ((t & 31) == 0) wsum[t >> 5] = ss;
    __syncthreads();
    float tot = wsum[0] + wsum[1] + wsum[2] + wsum[3];
    float r   = rsqrtf(tot * (1.f / 128.f) + 1e-6f);
    float xn  = v * r * w[t];
    sv[t] = xn;
    __syncthreads();

    int   d = (t < 64) ? t : (t - 64);
    float c = pe[(size_t)bs * 128 + d];
    float s = pe[(size_t)bs * 128 + 64 + d];
    float other = (t < 64) ? sv[t + 64] : sv[t - 64];
    float out   = (t < 64) ? (xn * c - other * s) : (other * s + xn * c);
    __nv_bfloat16 hi = __float2bfloat16(out);
    Xh[(size_t)row * 128 + t] = hi;
    Xl[(size_t)row * 128 + t] = __float2bfloat16(out - __bfloat162float(hi));
}

// ---------------------------------------------------------------------------
// Flash attention on tensor cores (bf16x3 both matmuls), causal GQA.
// BR=128 (8 warps x 16 rows), BC=64.
// Q fragments in registers; 3-stage KV ring, ONE __syncthreads per tile with
// correct ordering: wait_group -> barrier -> fill(kt+2) -> compute(kt).
// ---------------------------------------------------------------------------
#define FSTR   272u
#define FKH    0u
#define FKL    17408u
#define FVH    34816u
#define FVL    52224u
#define FSTGSZ 69632u
#define FLASH2_SMEM (3 * 69632)

__global__ __launch_bounds__(256, 1) void flash_mma(
    const __nv_bfloat16* __restrict__ Qh, const __nv_bfloat16* __restrict__ Ql,
    const __nv_bfloat16* __restrict__ Kh, const __nv_bfloat16* __restrict__ Kl,
    const __nv_bfloat16* __restrict__ Vh, const __nv_bfloat16* __restrict__ Vl,
    __nv_bfloat16* __restrict__ Oh, __nv_bfloat16* __restrict__ Ol)
{
    extern __shared__ __align__(16) char smem[];
    const uint32_t sb = smem_u32(smem);
    const int tid = threadIdx.x, lane = tid & 31, w = tid >> 5;
    const int bx = gridDim.x - 1 - blockIdx.x;   // heavy diagonals first
    const int h = blockIdx.y, b = blockIdx.z, kvh = h >> 1;
    const int g = lane >> 2, tg = lane & 3;
    const int ntiles = 2 * bx + 2;               // always >= 2

    // ---- prologue: cp.async Q into stage-2 region (group 0) ----
    {
        const size_t qbase = (((size_t)b * S_ + (size_t)bx * 128) * H_ + h) * D_;
        const uint32_t qdst = sb + 2u * FSTGSZ;
#pragma unroll
        for (int i = 0; i < 8; i++) {
            int idx = tid + i * 256;
            int r = idx >> 4, seg = idx & 15;
            size_t src = qbase + (size_t)r * (H_ * D_) + seg * 8;
            uint32_t dst = qdst + (uint32_t)r * FSTR + (uint32_t)seg * 16u;
            cpasync16(dst,          Qh + src);
            cpasync16(dst + 34816u, Ql + src);
        }
    }
    asm volatile("cp.async.commit_group;");

    auto fillKV = [&](int stage, int kt) {
        const size_t kbase = (((size_t)b * S_ + (size_t)kt * 64) * KV_ + kvh) * D_;
        const uint32_t sdst = sb + (uint32_t)stage * FSTGSZ;
#pragma unroll
        for (int i = 0; i < 4; i++) {
            int idx = tid + i * 256;
            int r = idx >> 4, seg = idx & 15;
            size_t src = kbase + (size_t)r * (KV_ * D_) + seg * 8;
            uint32_t dst = sdst + (uint32_t)r * FSTR + (uint32_t)seg * 16u;
            cpasync16(dst + FKH, Kh + src);
            cpasync16(dst + FKL, Kl + src);
            cpasync16(dst + FVH, Vh + src);
            cpasync16(dst + FVL, Vl + src);
        }
        asm volatile("cp.async.commit_group;");
    };

    fillKV(0, 0);          // group 1
    fillKV(1, 1);          // group 2   (ntiles >= 2 always)

    // Q complete (own portions) -> barrier -> all portions visible
    asm volatile("cp.async.wait_group 2;");
    __syncthreads();

    // ---- Q fragments -> registers (read stage-2 region) ----
    uint32_t qfh[8][4], qfl[8][4];
    {
        const uint32_t aQ = sb + 2u * FSTGSZ
                          + (uint32_t)(w * 16 + (lane & 15)) * FSTR
                          + (uint32_t)((lane >> 4) * 16);
#pragma unroll
        for (int kb = 0; kb < 8; kb++) {
            ldsm_x4(qfh[kb][0], qfh[kb][1], qfh[kb][2], qfh[kb][3], aQ + kb * 32);
            ldsm_x4(qfl[kb][0], qfl[kb][1], qfl[kb][2], qfl[kb][3],
                    aQ + 34816u + kb * 32);
        }
    }

    float o[16][4];
#pragma unroll
    for (int i = 0; i < 16; i++)
#pragma unroll
        for (int j = 0; j < 4; j++) o[i][j] = 0.f;
    float m0 = -1e30f, m1 = -1e30f, l0 = 0.f, l1 = 0.f;

    const int qr0 = bx * 128 + w * 16 + g;
    const float sca2 = 0.12751744f;   // log2(e)/sqrt(128)

    int cur = 0;
    for (int kt = 0; kt < ntiles; kt++) {
        // RAW: own fill(kt) complete, then barrier -> all portions visible.
        if (kt + 1 < ntiles) {
            asm volatile("cp.async.wait_group 1;");
        } else {
            asm volatile("cp.async.wait_group 0;");
        }
        __syncthreads();
        // WAR: stage (cur+2)%3 was read during iteration kt-1 (or Q prologue),
        // both ordered before this barrier -> safe to refill now.
        if (kt + 2 < ntiles) {
            int fs = cur + 2; if (fs >= 3) fs -= 3;
            fillKV(fs, kt + 2);
        }

        if (kt * 64 <= bx * 128 + w * 16 + 15) {   // warp has unmasked work
            const uint32_t stg = sb + (uint32_t)cur * FSTGSZ;
            const uint32_t bK  = stg + (uint32_t)((((lane >> 4) << 3) + (lane & 7)) * FSTR)
                               + (uint32_t)(((lane >> 3) & 1) * 16);

            // ---- S = Q K^T (bf16x3), Q from registers ----
            float sc[8][4];
#pragma unroll
            for (int i = 0; i < 8; i++)
#pragma unroll
                for (int j = 0; j < 4; j++) sc[i][j] = 0.f;

#pragma unroll
            for (int kb = 0; kb < 8; kb++) {
#pragma unroll
                for (int nt = 0; nt < 4; nt++) {
                    uint32_t kh0, kh1, kh2, kh3, kl0, kl1, kl2, kl3;
                    ldsm_x4(kh0, kh1, kh2, kh3,
                            bK + FKH + (uint32_t)(nt * 16) * FSTR + kb * 32);
                    ldsm_x4(kl0, kl1, kl2, kl3,
                            bK + FKL + (uint32_t)(nt * 16) * FSTR + kb * 32);
                    mma16816(sc[2 * nt],     qfh[kb], kh0, kh1);
                    mma16816(sc[2 * nt],     qfh[kb], kl0, kl1);
                    mma16816(sc[2 * nt],     qfl[kb], kh0, kh1);
                    mma16816(sc[2 * nt + 1], qfh[kb], kh2, kh3);
                    mma16816(sc[2 * nt + 1], qfh[kb], kl2, kl3);
                    mma16816(sc[2 * nt + 1], qfl[kb], kh2, kh3);
                }
            }

            // ---- scale (log2 domain) + causal mask ----
            const bool maskt = (kt * 64 + 63 > bx * 128 + w * 16);
            const int row0 = qr0, row1 = qr0 + 8, cb = kt * 64;
#pragma unroll
            for (int nt = 0; nt < 8; nt++) {
                int c0 = cb + nt * 8 + tg * 2;
                float v0 = sc[nt][0] * sca2, v1 = sc[nt][1] * sca2;
                float v2 = sc[nt][2] * sca2, v3 = sc[nt][3] * sca2;
                if (maskt) {
                    if (c0     > row0) v0 = -1e30f;
                    if (c0 + 1 > row0) v1 = -1e30f;
                    if (c0     > row1) v2 = -1e30f;
                    if (c0 + 1 > row1) v3 = -1e30f;
                }
                sc[nt][0] = v0; sc[nt][1] = v1; sc[nt][2] = v2; sc[nt][3] = v3;
            }

            // ---- row max ----
            float mx0 = -1e30f, mx1 = -1e30f;
#pragma unroll
            for (int nt = 0; nt < 8; nt++) {
                mx0 = fmaxf(mx0, fmaxf(sc[nt][0], sc[nt][1]));
                mx1 = fmaxf(mx1, fmaxf(sc[nt][2], sc[nt][3]));
            }
            mx0 = fmaxf(mx0, __shfl_xor_sync(0xffffffffu, mx0, 1));
            mx0 = fmaxf(mx0, __shfl_xor_sync(0xffffffffu, mx0, 2));
            mx1 = fmaxf(mx1, __shfl_xor_sync(0xffffffffu, mx1, 1));
            mx1 = fmaxf(mx1, __shfl_xor_sync(0xffffffffu, mx1, 2));
            const float mn0 = fmaxf(m0, mx0), mn1 = fmaxf(m1, mx1);
            const float al0 = exp2f(m0 - mn0), al1 = exp2f(m1 - mn1);
            m0 = mn0; m1 = mn1;
#pragma unroll
            for (int nt = 0; nt < 16; nt++) {
                o[nt][0] *= al0; o[nt][1] *= al0;
                o[nt][2] *= al1; o[nt][3] *= al1;
            }

            // ---- per-slice: exp2 -> pack -> PV (interleaved) ----
            float s0 = 0.f, s1 = 0.f;
#pragma unroll
            for (int j = 0; j < 4; j++) {
                float p00 = exp2f(sc[2 * j][0] - mn0);
                float p01 = exp2f(sc[2 * j][1] - mn0);
                float p02 = exp2f(sc[2 * j][2] - mn1);
                float p03 = exp2f(sc[2 * j][3] - mn1);
                float p10 = exp2f(sc[2 * j + 1][0] - mn0);
                float p11 = exp2f(sc[2 * j + 1][1] - mn0);
                float p12 = exp2f(sc[2 * j + 1][2] - mn1);
                float p13 = exp2f(sc[2 * j + 1][3] - mn1);
                s0 += (p00 + p01) + (p10 + p11);
                s1 += (p02 + p03) + (p12 + p13);

                uint32_t ph[4], pl[4];
                pk(p00, p01, ph[0], pl[0]);
                pk(p02, p03, ph[1], pl[1]);
                pk(p10, p11, ph[2], pl[2]);
                pk(p12, p13, ph[3], pl[3]);

                const uint32_t vrow = stg
                    + (uint32_t)((j * 16 + ((lane >> 3) & 1) * 8 + (lane & 7)) * FSTR)
                    + (uint32_t)((lane >> 4) * 16);
#pragma unroll
                for (int ntp = 0; ntp < 8; ntp++) {
                    uint32_t vh0, vh1, vh2, vh3, vl0, vl1, vl2, vl3;
                    LDSM_X4_T(vh0, vh1, vh2, vh3, vrow + FVH + ntp * 32);
                    LDSM_X4_T(vl0, vl1, vl2, vl3, vrow + FVL + ntp * 32);
                    mma16816(o[2 * ntp],     ph, vh0, vh1);
                    mma16816(o[2 * ntp],     ph, vl0, vl1);
                    mma16816(o[2 * ntp],     pl, vh0, vh1);
                    mma16816(o[2 * ntp + 1], ph, vh2, vh3);
                    mma16816(o[2 * ntp + 1], ph, vl2, vl3);
                    mma16816(o[2 * ntp + 1], pl, vh2, vh3);
                }
            }
            s0 += __shfl_xor_sync(0xffffffffu, s0, 1);
            s0 += __shfl_xor_sync(0xffffffffu, s0, 2);
            s1 += __shfl_xor_sync(0xffffffffu, s1, 1);
            s1 += __shfl_xor_sync(0xffffffffu, s1, 2);
            l0 = l0 * al0 + s0;
            l1 = l1 * al1 + s1;
        }
        if (++cur == 3) cur = 0;
    }

    // ---- epilogue: normalize, split to bf16 hi/lo, store ----
    const float i0 = 1.f / l0, i1 = 1.f / l1;
    const size_t o0 = (((size_t)b * S_ + (size_t)qr0) * H_ + h) * D_;
    const size_t o1 = o0 + (size_t)8 * (H_ * D_);
#pragma unroll
    for (int nt = 0; nt < 16; nt++) {
        const int col = nt * 8 + tg * 2;
        uint32_t hi, lo;
        pk(o[nt][0] * i0, o[nt][1] * i0, hi, lo);
        *(uint32_t*)&Oh[o0 + col] = hi;
        *(uint32_t*)&Ol[o0 + col] = lo;
        pk(o[nt][2] * i1, o[nt][3] * i1, hi, lo);
        *(uint32_t*)&Oh[o1 + col] = hi;
        *(uint32_t*)&Ol[o1 + col] = lo;
    }
}

// ---------------------------------------------------------------------------
extern "C" void kernel_launch(void* const* d_in, const int* in_sizes, int n_in,
                              void* d_out, int out_size)
{
    const float* x   = (const float*)d_in[0];
    const float* pe  = (const float*)d_in[1];
    const float* q_w = (const float*)d_in[2];
    const float* k_w = (const float*)d_in[3];
    const float* v_w = (const float*)d_in[4];
    const float* o_w = (const float*)d_in[5];
    const float* qnw = (const float*)d_in[6];
    const float* knw = (const float*)d_in[7];
    float* out = (float*)d_out;

    float *q, *k, *v;
    __nv_bfloat16 *qh, *ql, *kh, *kl, *vh, *vl;
    __nv_bfloat16 *xh, *xl, *qwh, *qwl, *kwh, *kwl, *vwh, *vwl, *owh, *owl, *ath, *atl;
    cudaGetSymbolAddress((void**)&q,   g_q);
    cudaGetSymbolAddress((void**)&k,   g_k);
    cudaGetSymbolAddress((void**)&v,   g_v);
    cudaGetSymbolAddress((void**)&qh,  g_qh2);
    cudaGetSymbolAddress((void**)&ql,  g_ql2);
    cudaGetSymbolAddress((void**)&kh,  g_kh2);
    cudaGetSymbolAddress((void**)&kl,  g_kl2);
    cudaGetSymbolAddress((void**)&vh,  g_vh2);
    cudaGetSymbolAddress((void**)&vl,  g_vl2);
    cudaGetSymbolAddress((void**)&xh,  g_xh);
    cudaGetSymbolAddress((void**)&xl,  g_xl);
    cudaGetSymbolAddress((void**)&qwh, g_qwh);
    cudaGetSymbolAddress((void**)&qwl, g_qwl);
    cudaGetSymbolAddress((void**)&kwh, g_kwh);
    cudaGetSymbolAddress((void**)&kwl, g_kwl);
    cudaGetSymbolAddress((void**)&vwh, g_vwh);
    cudaGetSymbolAddress((void**)&vwl, g_vwl);
    cudaGetSymbolAddress((void**)&owh, g_owh);
    cudaGetSymbolAddress((void**)&owl, g_owl);
    cudaGetSymbolAddress((void**)&ath, g_ath);
    cudaGetSymbolAddress((void**)&atl, g_atl);

    cudaFuncSetAttribute(gemm_bf16x3, cudaFuncAttributeMaxDynamicSharedMemorySize,
                         GEMM_SMEM);
    cudaFuncSetAttribute(gemm_qkv, cudaFuncAttributeMaxDynamicSharedMemorySize,
                         GEMM_SMEM);
    cudaFuncSetAttribute(flash_mma, cudaFuncAttributeMaxDynamicSharedMemorySize,
                         FLASH2_SMEM);

    // 1) bf16 hi/lo splits of x and weights
    const int nx  = MROWS * HID_ / 4;
    const int nqw = H_ * D_ * HID_ / 4;
    const int nkw = KV_ * D_ * HID_ / 4;
    split_bf16<<<(nx  + 255) / 256, 256>>>((const float4*)x,
        (__nv_bfloat162*)xh, (__nv_bfloat162*)xl, nx);
    split_bf16<<<(nqw + 255) / 256, 256>>>((const float4*)q_w,
        (__nv_bfloat162*)qwh, (__nv_bfloat162*)qwl, nqw);
    split_bf16<<<(nkw + 255) / 256, 256>>>((const float4*)k_w,
        (__nv_bfloat162*)kwh, (__nv_bfloat162*)kwl, nkw);
    split_bf16<<<(nkw + 255) / 256, 256>>>((const float4*)v_w,
        (__nv_bfloat162*)vwh, (__nv_bfloat162*)vwl, nkw);
    split_bf16<<<(nqw + 255) / 256, 256>>>((const float4*)o_w,
        (__nv_bfloat162*)owh, (__nv_bfloat162*)owl, nqw);

    // 2) Fused Q/K/V projections (bf16x3 mma.sync, one launch)
    gemm_qkv<<<dim3(32, 32), 256, GEMM_SMEM>>>(xh, xl, qwh, qwl, kwh, kwl,
                                               vwh, vwl, q, k, v, HID_);

    // 3) V split to bf16 hi/lo for tensor-core flash
    const int nv = MROWS * KV_ * D_ / 4;
    split_bf16<<<(nv + 255) / 256, 256>>>((const float4*)v,
        (__nv_bfloat162*)vh, (__nv_bfloat162*)vl, nv);

    // 4) Per-head RMSNorm + RoPE, output bf16 hi/lo
    rmsnorm_rope_b<<<MROWS * H_,  128>>>(q, pe, qnw, H_,  qh, ql);
    rmsnorm_rope_b<<<MROWS * KV_, 128>>>(k, pe, knw, KV_, kh, kl);

    // 5) Causal GQA flash attention on tensor cores
    flash_mma<<<dim3(S_ / 128, H_, B_), 256, FLASH2_SMEM>>>(
        qh, ql, kh, kl, vh, vl, ath, atl);

    // 6) Output projection (bf16x3 mma.sync)
    gemm_bf16x3<<<dim3(16, 32), 256, GEMM_SMEM>>>(ath, atl, owh, owl, out, HID_, HID_);
}

// round 11
// speedup vs baseline: 3.0625x; 1.0066x over previous
#include <cuda_runtime.h>
#include <cuda_bf16.h>
#include <math.h>
#include <stdint.h>

#define B_   2
#define S_   2048
#define HID_ 2048
#define H_   16
#define KV_  8
#define D_   128
#define MROWS (B_ * S_)   // 4096

// ---------------------------------------------------------------------------
// Scratch (__device__ globals; allocation-free rule)
// ---------------------------------------------------------------------------
__device__ float g_q[(size_t)MROWS * H_ * D_];
__device__ float g_k[(size_t)MROWS * KV_ * D_];
__device__ float g_v[(size_t)MROWS * KV_ * D_];
__device__ __nv_bfloat16 g_qh2[(size_t)MROWS * H_ * D_];
__device__ __nv_bfloat16 g_ql2[(size_t)MROWS * H_ * D_];
__device__ __nv_bfloat16 g_kh2[(size_t)MROWS * KV_ * D_];
__device__ __nv_bfloat16 g_kl2[(size_t)MROWS * KV_ * D_];
__device__ __nv_bfloat16 g_vh2[(size_t)MROWS * KV_ * D_];
__device__ __nv_bfloat16 g_vl2[(size_t)MROWS * KV_ * D_];
__device__ __nv_bfloat16 g_xh[(size_t)MROWS * HID_];
__device__ __nv_bfloat16 g_xl[(size_t)MROWS * HID_];
__device__ __nv_bfloat16 g_qwh[(size_t)H_ * D_ * HID_];
__device__ __nv_bfloat16 g_qwl[(size_t)H_ * D_ * HID_];
__device__ __nv_bfloat16 g_kwh[(size_t)KV_ * D_ * HID_];
__device__ __nv_bfloat16 g_kwl[(size_t)KV_ * D_ * HID_];
__device__ __nv_bfloat16 g_vwh[(size_t)KV_ * D_ * HID_];
__device__ __nv_bfloat16 g_vwl[(size_t)KV_ * D_ * HID_];
__device__ __nv_bfloat16 g_owh[(size_t)HID_ * H_ * D_];
__device__ __nv_bfloat16 g_owl[(size_t)HID_ * H_ * D_];
__device__ __nv_bfloat16 g_ath[(size_t)MROWS * H_ * D_];
__device__ __nv_bfloat16 g_atl[(size_t)MROWS * H_ * D_];

// ---------------------------------------------------------------------------
// Helpers
// ---------------------------------------------------------------------------
__device__ __forceinline__ uint32_t smem_u32(const void* p) {
    uint32_t a;
    asm("{ .reg .u64 t; cvta.to.shared.u64 t, %1; cvt.u32.u64 %0, t; }"
        : "=r"(a) : "l"(p));
    return a;
}

__device__ __forceinline__ void cpasync16(uint32_t dst, const void* src) {
    asm volatile("cp.async.cg.shared.global [%0], [%1], 16;" :: "r"(dst), "l"(src));
}

#define LDSM_X4(r0, r1, r2, r3, addr)                                         \
    asm volatile("ldmatrix.sync.aligned.m8n8.x4.shared.b16 {%0,%1,%2,%3}, [%4];" \
                 : "=r"(r0), "=r"(r1), "=r"(r2), "=r"(r3) : "r"(addr))

#define LDSM_X4_T(r0, r1, r2, r3, addr)                                       \
    asm volatile("ldmatrix.sync.aligned.m8n8.x4.trans.shared.b16 {%0,%1,%2,%3}, [%4];" \
                 : "=r"(r0), "=r"(r1), "=r"(r2), "=r"(r3) : "r"(addr))

__device__ __forceinline__ void ldsm_x4(uint32_t& r0, uint32_t& r1,
                                        uint32_t& r2, uint32_t& r3, uint32_t addr) {
    LDSM_X4(r0, r1, r2, r3, addr);
}

__device__ __forceinline__ void mma_bf16(float* c, const uint32_t* a, const uint32_t* b) {
    asm volatile("mma.sync.aligned.m16n8k16.row.col.f32.bf16.bf16.f32 "
                 "{%0,%1,%2,%3}, {%4,%5,%6,%7}, {%8,%9}, {%0,%1,%2,%3};"
                 : "+f"(c[0]), "+f"(c[1]), "+f"(c[2]), "+f"(c[3])
                 : "r"(a[0]), "r"(a[1]), "r"(a[2]), "r"(a[3]),
                   "r"(b[0]), "r"(b[1]));
}
__device__ __forceinline__ void mma16816(float* c, const uint32_t* a,
                                         uint32_t b0, uint32_t b1) {
    asm volatile("mma.sync.aligned.m16n8k16.row.col.f32.bf16.bf16.f32 "
                 "{%0,%1,%2,%3}, {%4,%5,%6,%7}, {%8,%9}, {%0,%1,%2,%3};"
                 : "+f"(c[0]), "+f"(c[1]), "+f"(c[2]), "+f"(c[3])
                 : "r"(a[0]), "r"(a[1]), "r"(a[2]), "r"(a[3]), "r"(b0), "r"(b1));
}

// pack (a,b) fp32 -> bf16x2 hi and residual bf16x2 lo
__device__ __forceinline__ void pk(float a, float b, uint32_t& hi, uint32_t& lo) {
    __nv_bfloat16 ha = __float2bfloat16(a), hb = __float2bfloat16(b);
    __nv_bfloat16 la = __float2bfloat16(a - __bfloat162float(ha));
    __nv_bfloat16 lb = __float2bfloat16(b - __bfloat162float(hb));
    hi = ((uint32_t)*(uint16_t*)&hb << 16) | (uint32_t)*(uint16_t*)&ha;
    lo = ((uint32_t)*(uint16_t*)&lb << 16) | (uint32_t)*(uint16_t*)&la;
}

// ---------------------------------------------------------------------------
// split helper + fused 5-array split kernel (x, qw, kw, vw, ow)
// ---------------------------------------------------------------------------
__device__ __forceinline__ void split1(const float4* __restrict__ s,
                                       __nv_bfloat162* __restrict__ h,
                                       __nv_bfloat162* __restrict__ l, int i)
{
    float4 v = s[i];
    __nv_bfloat16 hx = __float2bfloat16(v.x);
    __nv_bfloat16 hy = __float2bfloat16(v.y);
    __nv_bfloat16 hz = __float2bfloat16(v.z);
    __nv_bfloat16 hw = __float2bfloat16(v.w);
    __nv_bfloat16 lx = __float2bfloat16(v.x - __bfloat162float(hx));
    __nv_bfloat16 ly = __float2bfloat16(v.y - __bfloat162float(hy));
    __nv_bfloat16 lz = __float2bfloat16(v.z - __bfloat162float(hz));
    __nv_bfloat16 lw = __float2bfloat16(v.w - __bfloat162float(hw));
    h[2 * i]     = __nv_bfloat162(hx, hy);
    h[2 * i + 1] = __nv_bfloat162(hz, hw);
    l[2 * i]     = __nv_bfloat162(lx, ly);
    l[2 * i + 1] = __nv_bfloat162(lz, lw);
}

#define NX4  (MROWS * HID_ / 4)        // 2097152
#define NQW4 (H_ * D_ * HID_ / 4)      // 1048576
#define NKW4 (KV_ * D_ * HID_ / 4)     // 524288
#define NSPLIT_TOT (NX4 + 2 * NQW4 + 2 * NKW4)   // 5242880

__global__ __launch_bounds__(256) void split5(
    const float4* __restrict__ x,  const float4* __restrict__ qw,
    const float4* __restrict__ kw, const float4* __restrict__ vw,
    const float4* __restrict__ ow,
    __nv_bfloat162* xh, __nv_bfloat162* xl,
    __nv_bfloat162* qwh, __nv_bfloat162* qwl,
    __nv_bfloat162* kwh, __nv_bfloat162* kwl,
    __nv_bfloat162* vwh, __nv_bfloat162* vwl,
    __nv_bfloat162* owh, __nv_bfloat162* owl)
{
    int i = blockIdx.x * 256 + threadIdx.x;
    if (i < NX4) { split1(x, xh, xl, i); return; }
    i -= NX4;
    if (i < NQW4) { split1(qw, qwh, qwl, i); return; }
    i -= NQW4;
    if (i < NKW4) { split1(kw, kwh, kwl, i); return; }
    i -= NKW4;
    if (i < NKW4) { split1(vw, vwh, vwl, i); return; }
    i -= NKW4;
    split1(ow, owh, owl, i);
}

// ---------------------------------------------------------------------------
// bf16x3 mma.sync GEMM body (validated): C[m,n] = sum_k A[m,k]*B[n,k]
// ---------------------------------------------------------------------------
#define GK_      32
#define RSTR_B   80u
#define TILE_B   (128u * RSTR_B)
#define STAGE_B  (4u * TILE_B)
#define GEMM_SMEM (2 * 40960)

__device__ __forceinline__ void g_fill(
    uint32_t dst, const __nv_bfloat16* Ah, const __nv_bfloat16* Al,
    const __nv_bfloat16* Bh, const __nv_bfloat16* Bl,
    int m0, int n0, int K, int k0, int tid)
{
#pragma unroll
    for (int i = 0; i < 8; i++) {
        int idx = tid + i * 256;
        int t   = idx >> 9;
        int rem = idx & 511;
        int r   = rem >> 2;
        int seg = rem & 3;
        const __nv_bfloat16* src;
        if      (t == 0) src = Ah + (size_t)(m0 + r) * K + k0 + seg * 8;
        else if (t == 1) src = Al + (size_t)(m0 + r) * K + k0 + seg * 8;
        else if (t == 2) src = Bh + (size_t)(n0 + r) * K + k0 + seg * 8;
        else             src = Bl + (size_t)(n0 + r) * K + k0 + seg * 8;
        uint32_t d = dst + (uint32_t)t * TILE_B + (uint32_t)r * RSTR_B + (uint32_t)seg * 16u;
        cpasync16(d, src);
    }
}

__device__ __forceinline__ void gemm_body(
    const __nv_bfloat16* Ah, const __nv_bfloat16* Al,
    const __nv_bfloat16* Bh, const __nv_bfloat16* Bl,
    float* C, int N, int K, int m0, int n0, char* smem)
{
    const uint32_t sb  = smem_u32(smem);
    const int tid  = threadIdx.x;
    const int wid  = tid >> 5, lane = tid & 31;
    const int wm   = (wid >> 2) << 6;
    const int wn   = (wid & 3)  << 5;

    const uint32_t aoff = (uint32_t)(wm + (lane & 15)) * RSTR_B + (uint32_t)((lane >> 4) * 16);
    const uint32_t boff = (uint32_t)(wn + ((lane >> 4) << 3) + (lane & 7)) * RSTR_B
                        + (uint32_t)(((lane >> 3) & 1) * 16);

    float acc[4][4][4];
#pragma unroll
    for (int mi = 0; mi < 4; mi++)
#pragma unroll
        for (int ni = 0; ni < 4; ni++)
#pragma unroll
            for (int r = 0; r < 4; r++) acc[mi][ni][r] = 0.f;

    g_fill(sb, Ah, Al, Bh, Bl, m0, n0, K, 0, tid);
    asm volatile("cp.async.commit_group;");

    const int nit = K / GK_;
    for (int it = 0; it < nit; ++it) {
        const int cur = it & 1;
        if (it + 1 < nit) {
            g_fill(sb + (uint32_t)(cur ^ 1) * STAGE_B, Ah, Al, Bh, Bl,
                   m0, n0, K, (it + 1) * GK_, tid);
            asm volatile("cp.async.commit_group;");
            asm volatile("cp.async.wait_group 1;");
        } else {
            asm volatile("cp.async.wait_group 0;");
        }
        __syncthreads();

        const uint32_t stg = sb + (uint32_t)cur * STAGE_B;
        const uint32_t sAh = stg;
        const uint32_t sAl = stg + TILE_B;
        const uint32_t sBh = stg + 2u * TILE_B;
        const uint32_t sBl = stg + 3u * TILE_B;

#pragma unroll
        for (int kh = 0; kh < 2; kh++) {
            const uint32_t kb = (uint32_t)kh * 32u;
            uint32_t ah[4][4], al[4][4], bh[4][2], bl[4][2];
#pragma unroll
            for (int mi = 0; mi < 4; mi++) {
                ldsm_x4(ah[mi][0], ah[mi][1], ah[mi][2], ah[mi][3],
                        sAh + aoff + (uint32_t)(mi * 16) * RSTR_B + kb);
                ldsm_x4(al[mi][0], al[mi][1], al[mi][2], al[mi][3],
                        sAl + aoff + (uint32_t)(mi * 16) * RSTR_B + kb);
            }
#pragma unroll
            for (int nt = 0; nt < 2; nt++) {
                uint32_t r0, r1, r2, r3;
                ldsm_x4(r0, r1, r2, r3, sBh + boff + (uint32_t)(nt * 16) * RSTR_B + kb);
                bh[nt * 2 + 0][0] = r0; bh[nt * 2 + 0][1] = r1;
                bh[nt * 2 + 1][0] = r2; bh[nt * 2 + 1][1] = r3;
                ldsm_x4(r0, r1, r2, r3, sBl + boff + (uint32_t)(nt * 16) * RSTR_B + kb);
                bl[nt * 2 + 0][0] = r0; bl[nt * 2 + 0][1] = r1;
                bl[nt * 2 + 1][0] = r2; bl[nt * 2 + 1][1] = r3;
            }
#pragma unroll
            for (int mi = 0; mi < 4; mi++)
#pragma unroll
                for (int ni = 0; ni < 4; ni++) {
                    mma_bf16(acc[mi][ni], ah[mi], bh[ni]);
                    mma_bf16(acc[mi][ni], ah[mi], bl[ni]);
                    mma_bf16(acc[mi][ni], al[mi], bh[ni]);
                }
        }
        __syncthreads();
    }

#pragma unroll
    for (int mi = 0; mi < 4; mi++) {
        const int row = m0 + wm + mi * 16 + (lane >> 2);
#pragma unroll
        for (int ni = 0; ni < 4; ni++) {
            const int col = n0 + wn + ni * 8 + (lane & 3) * 2;
            *(float2*)&C[(size_t)row * N + col] =
                make_float2(acc[mi][ni][0], acc[mi][ni][1]);
            *(float2*)&C[(size_t)(row + 8) * N + col] =
                make_float2(acc[mi][ni][2], acc[mi][ni][3]);
        }
    }
}

__global__ __launch_bounds__(256, 1) void gemm_bf16x3(
    const __nv_bfloat16* __restrict__ Ah, const __nv_bfloat16* __restrict__ Al,
    const __nv_bfloat16* __restrict__ Bh, const __nv_bfloat16* __restrict__ Bl,
    float* __restrict__ C, int N, int K)
{
    extern __shared__ __align__(128) char smem[];
    gemm_body(Ah, Al, Bh, Bl, C, N, K, blockIdx.y << 7, blockIdx.x << 7, smem);
}

// Fused Q/K/V projection: one launch, per-block weight/output select.
__global__ __launch_bounds__(256, 1) void gemm_qkv(
    const __nv_bfloat16* __restrict__ xh, const __nv_bfloat16* __restrict__ xl,
    const __nv_bfloat16* __restrict__ qwh, const __nv_bfloat16* __restrict__ qwl,
    const __nv_bfloat16* __restrict__ kwh, const __nv_bfloat16* __restrict__ kwl,
    const __nv_bfloat16* __restrict__ vwh, const __nv_bfloat16* __restrict__ vwl,
    float* __restrict__ q, float* __restrict__ k, float* __restrict__ v, int K)
{
    extern __shared__ __align__(128) char smem[];
    const int bxx = blockIdx.x;
    const __nv_bfloat16 *Bh, *Bl;
    float* C; int N, n0;
    if (bxx < 16)      { Bh = qwh; Bl = qwl; C = q; N = 2048; n0 = bxx << 7; }
    else if (bxx < 24) { Bh = kwh; Bl = kwl; C = k; N = 1024; n0 = (bxx - 16) << 7; }
    else               { Bh = vwh; Bl = vwl; C = v; N = 1024; n0 = (bxx - 24) << 7; }
    gemm_body(xh, xl, Bh, Bl, C, N, K, blockIdx.y << 7, n0, smem);
}

// ---------------------------------------------------------------------------
// Fused prep: rmsnorm+rope for Q and K, plus bf16 split of V. 128 threads.
// blocks [0, 65536): rms q | [65536, 98304): rms k | [98304, +8192): split v
// ---------------------------------------------------------------------------
__device__ __forceinline__ void rms_rope_body(
    const float* __restrict__ X, const float* __restrict__ pe,
    const float* __restrict__ w, int nheads, int row,
    __nv_bfloat16* __restrict__ Xh, __nv_bfloat16* __restrict__ Xl,
    float* sv, float* wsum)
{
    const int t  = threadIdx.x;
    const int bs = row / nheads;

    float v  = X[(size_t)row * 128 + t];
    float ss = v * v;
#pragma unroll
    for (int o = 16; o > 0; o >>= 1) ss += __shfl_xor_sync(0xffffffffu, ss, o);
    if ((t & 31) == 0) wsum[t >> 5] = ss;
    __syncthreads();
    float tot = wsum[0] + wsum[1] + wsum[2] + wsum[3];
    float r   = rsqrtf(tot * (1.f / 128.f) + 1e-6f);
    float xn  = v * r * w[t];
    sv[t] = xn;
    __syncthreads();

    int   d = (t < 64) ? t : (t - 64);
    float c = pe[(size_t)bs * 128 + d];
    float s = pe[(size_t)bs * 128 + 64 + d];
    float other = (t < 64) ? sv[t + 64] : sv[t - 64];
    float out   = (t < 64) ? (xn * c - other * s) : (other * s + xn * c);
    __nv_bfloat16 hi = __float2bfloat16(out);
    Xh[(size_t)row * 128 + t] = hi;
    Xl[(size_t)row * 128 + t] = __float2bfloat16(out - __bfloat162float(hi));
}

__global__ __launch_bounds__(128) void prep_fused(
    const float* __restrict__ q, const float* __restrict__ k,
    const float* __restrict__ v, const float* __restrict__ pe,
    const float* __restrict__ qnw, const float* __restrict__ knw,
    __nv_bfloat16* qh, __nv_bfloat16* ql,
    __nv_bfloat16* kh, __nv_bfloat16* kl,
    __nv_bfloat16* vh, __nv_bfloat16* vl)
{
    __shared__ float sv[128];
    __shared__ float wsum[4];
    const int bid = blockIdx.x;
    if (bid < MROWS * H_) {
        rms_rope_body(q, pe, qnw, H_, bid, qh, ql, sv, wsum);
    } else if (bid < MROWS * H_ + MROWS * KV_) {
        rms_rope_body(k, pe, knw, KV_, bid - MROWS * H_, kh, kl, sv, wsum);
    } else {
        int i = (bid - (MROWS * H_ + MROWS * KV_)) * 128 + threadIdx.x;
        split1((const float4*)v, (__nv_bfloat162*)vh, (__nv_bfloat162*)vl, i);
    }
}

// ---------------------------------------------------------------------------
// Flash attention on tensor cores (bf16x3 both matmuls), causal GQA.
// BR=64 (4 warps x 16 rows), BC=32, 3-stage KV ring, 2 CTAs/SM.
// Q fragments in registers. Ordering: wait -> barrier -> fill(kt+2) -> compute.
// ---------------------------------------------------------------------------
#define F2STR   272u
#define F2_KH   0u
#define F2_KL   8704u
#define F2_VH   17408u
#define F2_VL   26112u
#define F2_STG  34816u
#define FLASH3_SMEM (3 * 34816)   // 104448

__global__ __launch_bounds__(128, 2) void flash_mma(
    const __nv_bfloat16* __restrict__ Qh, const __nv_bfloat16* __restrict__ Ql,
    const __nv_bfloat16* __restrict__ Kh, const __nv_bfloat16* __restrict__ Kl,
    const __nv_bfloat16* __restrict__ Vh, const __nv_bfloat16* __restrict__ Vl,
    __nv_bfloat16* __restrict__ Oh, __nv_bfloat16* __restrict__ Ol)
{
    extern __shared__ __align__(16) char smem[];
    const uint32_t sb = smem_u32(smem);
    const int tid = threadIdx.x, lane = tid & 31, w = tid >> 5;   // w in 0..3
    const int bx = gridDim.x - 1 - blockIdx.x;   // heavy diagonals first
    const int h = blockIdx.y, b = blockIdx.z, kvh = h >> 1;
    const int g = lane >> 2, tg = lane & 3;
    const int ntiles = 2 * bx + 2;               // BC=32 tiles; always >= 2

    // ---- prologue: cp.async Q (64 rows x 128, hi+lo) into stage-2 region ----
    {
        const size_t qbase = (((size_t)b * S_ + (size_t)bx * 64) * H_ + h) * D_;
        const uint32_t qdst = sb + 2u * F2_STG;
#pragma unroll
        for (int i = 0; i < 8; i++) {
            int idx = tid + i * 128;
            int r = idx >> 4, seg = idx & 15;
            size_t src = qbase + (size_t)r * (H_ * D_) + seg * 8;
            uint32_t dst = qdst + (uint32_t)r * F2STR + (uint32_t)seg * 16u;
            cpasync16(dst,          Qh + src);
            cpasync16(dst + 17408u, Ql + src);
        }
    }
    asm volatile("cp.async.commit_group;");

    auto fillKV = [&](int stage, int kt) {
        const size_t kbase = (((size_t)b * S_ + (size_t)kt * 32) * KV_ + kvh) * D_;
        const uint32_t sdst = sb + (uint32_t)stage * F2_STG;
#pragma unroll
        for (int i = 0; i < 4; i++) {
            int idx = tid + i * 128;
            int r = idx >> 4, seg = idx & 15;
            size_t src = kbase + (size_t)r * (KV_ * D_) + seg * 8;
            uint32_t dst = sdst + (uint32_t)r * F2STR + (uint32_t)seg * 16u;
            cpasync16(dst + F2_KH, Kh + src);
            cpasync16(dst + F2_KL, Kl + src);
            cpasync16(dst + F2_VH, Vh + src);
            cpasync16(dst + F2_VL, Vl + src);
        }
        asm volatile("cp.async.commit_group;");
    };

    fillKV(0, 0);          // group 1
    fillKV(1, 1);          // group 2   (ntiles >= 2 always)

    asm volatile("cp.async.wait_group 2;");   // Q complete (own portions)
    __syncthreads();                          // all portions visible

    // ---- Q fragments -> registers ----
    uint32_t qfh[8][4], qfl[8][4];
    {
        const uint32_t aQ = sb + 2u * F2_STG
                          + (uint32_t)(w * 16 + (lane & 15)) * F2STR
                          + (uint32_t)((lane >> 4) * 16);
#pragma unroll
        for (int kb = 0; kb < 8; kb++) {
            ldsm_x4(qfh[kb][0], qfh[kb][1], qfh[kb][2], qfh[kb][3], aQ + kb * 32);
            ldsm_x4(qfl[kb][0], qfl[kb][1], qfl[kb][2], qfl[kb][3],
                    aQ + 17408u + kb * 32);
        }
    }

    float o[16][4];
#pragma unroll
    for (int i = 0; i < 16; i++)
#pragma unroll
        for (int j = 0; j < 4; j++) o[i][j] = 0.f;
    float m0 = -1e30f, m1 = -1e30f, l0 = 0.f, l1 = 0.f;

    const int qr0 = bx * 64 + w * 16 + g;
    const float sca2 = 0.12751744f;   // log2(e)/sqrt(128)

    int cur = 0;
    for (int kt = 0; kt < ntiles; kt++) {
        // RAW: own fill(kt) complete, then barrier -> all portions visible.
        if (kt + 1 < ntiles) {
            asm volatile("cp.async.wait_group 1;");
        } else {
            asm volatile("cp.async.wait_group 0;");
        }
        __syncthreads();
        // WAR: stage (cur+2)%3 last read at kt-1 (or Q prologue) -> refill OK.
        if (kt + 2 < ntiles) {
            int fs = cur + 2; if (fs >= 3) fs -= 3;
            fillKV(fs, kt + 2);
        }

        if (kt * 32 <= bx * 64 + w * 16 + 15) {   // warp has unmasked work
            const uint32_t stg = sb + (uint32_t)cur * F2_STG;
            const uint32_t bK  = stg + (uint32_t)((((lane >> 4) << 3) + (lane & 7)) * F2STR)
                               + (uint32_t)(((lane >> 3) & 1) * 16);

            // ---- S = Q K^T (bf16x3), Q from registers; 16 rows x 32 cols ----
            float sc[4][4];
#pragma unroll
            for (int i = 0; i < 4; i++)
#pragma unroll
                for (int j = 0; j < 4; j++) sc[i][j] = 0.f;

#pragma unroll
            for (int kb = 0; kb < 8; kb++) {
#pragma unroll
                for (int nt = 0; nt < 2; nt++) {
                    uint32_t kh0, kh1, kh2, kh3, kl0, kl1, kl2, kl3;
                    ldsm_x4(kh0, kh1, kh2, kh3,
                            bK + F2_KH + (uint32_t)(nt * 16) * F2STR + kb * 32);
                    ldsm_x4(kl0, kl1, kl2, kl3,
                            bK + F2_KL + (uint32_t)(nt * 16) * F2STR + kb * 32);
                    mma16816(sc[2 * nt],     qfh[kb], kh0, kh1);
                    mma16816(sc[2 * nt],     qfh[kb], kl0, kl1);
                    mma16816(sc[2 * nt],     qfl[kb], kh0, kh1);
                    mma16816(sc[2 * nt + 1], qfh[kb], kh2, kh3);
                    mma16816(sc[2 * nt + 1], qfh[kb], kl2, kl3);
                    mma16816(sc[2 * nt + 1], qfl[kb], kh2, kh3);
                }
            }

            // ---- scale (log2 domain) + causal mask ----
            const bool maskt = (kt * 32 + 31 > bx * 64 + w * 16);
            const int row0 = qr0, row1 = qr0 + 8, cb = kt * 32;
#pragma unroll
            for (int nt = 0; nt < 4; nt++) {
                int c0 = cb + nt * 8 + tg * 2;
                float v0 = sc[nt][0] * sca2, v1 = sc[nt][1] * sca2;
                float v2 = sc[nt][2] * sca2, v3 = sc[nt][3] * sca2;
                if (maskt) {
                    if (c0     > row0) v0 = -1e30f;
                    if (c0 + 1 > row0) v1 = -1e30f;
                    if (c0     > row1) v2 = -1e30f;
                    if (c0 + 1 > row1) v3 = -1e30f;
                }
                sc[nt][0] = v0; sc[nt][1] = v1; sc[nt][2] = v2; sc[nt][3] = v3;
            }

            // ---- row max ----
            float mx0 = -1e30f, mx1 = -1e30f;
#pragma unroll
            for (int nt = 0; nt < 4; nt++) {
                mx0 = fmaxf(mx0, fmaxf(sc[nt][0], sc[nt][1]));
                mx1 = fmaxf(mx1, fmaxf(sc[nt][2], sc[nt][3]));
            }
            mx0 = fmaxf(mx0, __shfl_xor_sync(0xffffffffu, mx0, 1));
            mx0 = fmaxf(mx0, __shfl_xor_sync(0xffffffffu, mx0, 2));
            mx1 = fmaxf(mx1, __shfl_xor_sync(0xffffffffu, mx1, 1));
            mx1 = fmaxf(mx1, __shfl_xor_sync(0xffffffffu, mx1, 2));
            const float mn0 = fmaxf(m0, mx0), mn1 = fmaxf(m1, mx1);
            const float al0 = exp2f(m0 - mn0), al1 = exp2f(m1 - mn1);
            m0 = mn0; m1 = mn1;
#pragma unroll
            for (int nt = 0; nt < 16; nt++) {
                o[nt][0] *= al0; o[nt][1] *= al0;
                o[nt][2] *= al1; o[nt][3] *= al1;
            }

            // ---- per-slice (2 x k16): exp2 -> pack -> PV ----
            float s0 = 0.f, s1 = 0.f;
#pragma unroll
            for (int j = 0; j < 2; j++) {
                float p00 = exp2f(sc[2 * j][0] - mn0);
                float p01 = exp2f(sc[2 * j][1] - mn0);
                float p02 = exp2f(sc[2 * j][2] - mn1);
                float p03 = exp2f(sc[2 * j][3] - mn1);
                float p10 = exp2f(sc[2 * j + 1][0] - mn0);
                float p11 = exp2f(sc[2 * j + 1][1] - mn0);
                float p12 = exp2f(sc[2 * j + 1][2] - mn1);
                float p13 = exp2f(sc[2 * j + 1][3] - mn1);
                s0 += (p00 + p01) + (p10 + p11);
                s1 += (p02 + p03) + (p12 + p13);

                uint32_t ph[4], pl[4];
                pk(p00, p01, ph[0], pl[0]);
                pk(p02, p03, ph[1], pl[1]);
                pk(p10, p11, ph[2], pl[2]);
                pk(p12, p13, ph[3], pl[3]);

                const uint32_t vrow = stg
                    + (uint32_t)((j * 16 + ((lane >> 3) & 1) * 8 + (lane & 7)) * F2STR)
                    + (uint32_t)((lane >> 4) * 16);
#pragma unroll
                for (int ntp = 0; ntp < 8; ntp++) {
                    uint32_t vh0, vh1, vh2, vh3, vl0, vl1, vl2, vl3;
                    LDSM_X4_T(vh0, vh1, vh2, vh3, vrow + F2_VH + ntp * 32);
                    LDSM_X4_T(vl0, vl1, vl2, vl3, vrow + F2_VL + ntp * 32);
                    mma16816(o[2 * ntp],     ph, vh0, vh1);
                    mma16816(o[2 * ntp],     ph, vl0, vl1);
                    mma16816(o[2 * ntp],     pl, vh0, vh1);
                    mma16816(o[2 * ntp + 1], ph, vh2, vh3);
                    mma16816(o[2 * ntp + 1], ph, vl2, vl3);
                    mma16816(o[2 * ntp + 1], pl, vh2, vh3);
                }
            }
            s0 += __shfl_xor_sync(0xffffffffu, s0, 1);
            s0 += __shfl_xor_sync(0xffffffffu, s0, 2);
            s1 += __shfl_xor_sync(0xffffffffu, s1, 1);
            s1 += __shfl_xor_sync(0xffffffffu, s1, 2);
            l0 = l0 * al0 + s0;
            l1 = l1 * al1 + s1;
        }
        if (++cur == 3) cur = 0;
    }

    // ---- epilogue: normalize, split to bf16 hi/lo, store ----
    const float i0 = 1.f / l0, i1 = 1.f / l1;
    const size_t o0 = (((size_t)b * S_ + (size_t)qr0) * H_ + h) * D_;
    const size_t o1 = o0 + (size_t)8 * (H_ * D_);
#pragma unroll
    for (int nt = 0; nt < 16; nt++) {
        const int col = nt * 8 + tg * 2;
        uint32_t hi, lo;
        pk(o[nt][0] * i0, o[nt][1] * i0, hi, lo);
        *(uint32_t*)&Oh[o0 + col] = hi;
        *(uint32_t*)&Ol[o0 + col] = lo;
        pk(o[nt][2] * i1, o[nt][3] * i1, hi, lo);
        *(uint32_t*)&Oh[o1 + col] = hi;
        *(uint32_t*)&Ol[o1 + col] = lo;
    }
}

// ---------------------------------------------------------------------------
extern "C" void kernel_launch(void* const* d_in, const int* in_sizes, int n_in,
                              void* d_out, int out_size)
{
    const float* x   = (const float*)d_in[0];
    const float* pe  = (const float*)d_in[1];
    const float* q_w = (const float*)d_in[2];
    const float* k_w = (const float*)d_in[3];
    const float* v_w = (const float*)d_in[4];
    const float* o_w = (const float*)d_in[5];
    const float* qnw = (const float*)d_in[6];
    const float* knw = (const float*)d_in[7];
    float* out = (float*)d_out;

    float *q, *k, *v;
    __nv_bfloat16 *qh, *ql, *kh, *kl, *vh, *vl;
    __nv_bfloat16 *xh, *xl, *qwh, *qwl, *kwh, *kwl, *vwh, *vwl, *owh, *owl, *ath, *atl;
    cudaGetSymbolAddress((void**)&q,   g_q);
    cudaGetSymbolAddress((void**)&k,   g_k);
    cudaGetSymbolAddress((void**)&v,   g_v);
    cudaGetSymbolAddress((void**)&qh,  g_qh2);
    cudaGetSymbolAddress((void**)&ql,  g_ql2);
    cudaGetSymbolAddress((void**)&kh,  g_kh2);
    cudaGetSymbolAddress((void**)&kl,  g_kl2);
    cudaGetSymbolAddress((void**)&vh,  g_vh2);
    cudaGetSymbolAddress((void**)&vl,  g_vl2);
    cudaGetSymbolAddress((void**)&xh,  g_xh);
    cudaGetSymbolAddress((void**)&xl,  g_xl);
    cudaGetSymbolAddress((void**)&qwh, g_qwh);
    cudaGetSymbolAddress((void**)&qwl, g_qwl);
    cudaGetSymbolAddress((void**)&kwh, g_kwh);
    cudaGetSymbolAddress((void**)&kwl, g_kwl);
    cudaGetSymbolAddress((void**)&vwh, g_vwh);
    cudaGetSymbolAddress((void**)&vwl, g_vwl);
    cudaGetSymbolAddress((void**)&owh, g_owh);
    cudaGetSymbolAddress((void**)&owl, g_owl);
    cudaGetSymbolAddress((void**)&ath, g_ath);
    cudaGetSymbolAddress((void**)&atl, g_atl);

    cudaFuncSetAttribute(gemm_bf16x3, cudaFuncAttributeMaxDynamicSharedMemorySize,
                         GEMM_SMEM);
    cudaFuncSetAttribute(gemm_qkv, cudaFuncAttributeMaxDynamicSharedMemorySize,
                         GEMM_SMEM);
    cudaFuncSetAttribute(flash_mma, cudaFuncAttributeMaxDynamicSharedMemorySize,
                         FLASH3_SMEM);

    // 1) fused bf16 hi/lo splits of x and all weights (one launch)
    split5<<<NSPLIT_TOT / 256, 256>>>(
        (const float4*)x, (const float4*)q_w, (const float4*)k_w,
        (const float4*)v_w, (const float4*)o_w,
        (__nv_bfloat162*)xh,  (__nv_bfloat162*)xl,
        (__nv_bfloat162*)qwh, (__nv_bfloat162*)qwl,
        (__nv_bfloat162*)kwh, (__nv_bfloat162*)kwl,
        (__nv_bfloat162*)vwh, (__nv_bfloat162*)vwl,
        (__nv_bfloat162*)owh, (__nv_bfloat162*)owl);

    // 2) fused Q/K/V projections (bf16x3 mma.sync, one launch)
    gemm_qkv<<<dim3(32, 32), 256, GEMM_SMEM>>>(xh, xl, qwh, qwl, kwh, kwl,
                                               vwh, vwl, q, k, v, HID_);

    // 3) fused prep: rms+rope(Q), rms+rope(K), split(V)  (one launch)
    const int nv4 = MROWS * KV_ * D_ / 4;                 // 1048576
    prep_fused<<<MROWS * H_ + MROWS * KV_ + nv4 / 128, 128>>>(
        q, k, v, pe, qnw, knw, qh, ql, kh, kl, vh, vl);

    // 4) causal GQA flash attention (2 CTAs/SM, BR=64, BC=32)  [launch #4]
    flash_mma<<<dim3(S_ / 64, H_, B_), 128, FLASH3_SMEM>>>(
        qh, ql, kh, kl, vh, vl, ath, atl);

    // 5) output projection (bf16x3 mma.sync)
    gemm_bf16x3<<<dim3(16, 32), 256, GEMM_SMEM>>>(ath, atl, owh, owl, out, HID_, HID_);
}